// round 1
// baseline (speedup 1.0000x reference)
#include <cuda_runtime.h>
#include <math.h>

#define NN 100000
#define EE 1600000
#define IN_CH 64
#define HH 128
#define H3 384
#define GG 4096

// ---------------- scratch (no allocations allowed) ----------------
__device__ float d_x0[NN * HH];
__device__ float d_xw[NN * HH];
__device__ float d_h[NN * HH];
__device__ float d_xc[NN * HH];
__device__ float d_gi[NN * H3];
__device__ float d_gh[NN * H3];
__device__ float d_asrc[NN];
__device__ float d_adst[NN];
__device__ float d_segmax[NN];
__device__ float d_segsum[NN];
__device__ float d_logit[EE];
__device__ float d_outG[GG * HH];
__device__ float d_hG[GG * HH];
__device__ float d_giG[GG * H3];
__device__ float d_ghG[GG * H3];
__device__ float d_adstG[GG];
__device__ float d_segmaxG[GG];
__device__ float d_segsumG[GG];
__device__ float d_vvec[HH];

// ---------------- helpers ----------------
__device__ __forceinline__ float warp_sum(float v) {
#pragma unroll
    for (int o = 16; o > 0; o >>= 1) v += __shfl_down_sync(0xffffffffu, v, o);
    return v;
}

__device__ __forceinline__ void atomicMaxFloat(float* addr, float v) {
    if (v >= 0.f)
        atomicMax((int*)addr, __float_as_int(v));
    else
        atomicMin((unsigned int*)addr, __float_as_uint(v));
}

// ---------------- generic fp32 GEMM: C[M,N] = A[M,K] @ B[N,K]^T (+bias, act) ----------------
// act: 0 = none, 1 = leaky_relu(0.01)
__global__ void sgemm(const float* __restrict__ A, const float* __restrict__ B,
                      const float* __restrict__ bias, float* __restrict__ C,
                      int M, int N, int K, int ldb, int act) {
    __shared__ float As[16][65];
    __shared__ float Bs[16][65];
    int row0 = blockIdx.y * 64;
    int col0 = blockIdx.x * 64;
    int tid = threadIdx.x;
    int tx = tid & 15, ty = tid >> 4;
    float acc[4][4] = {};
    for (int k0 = 0; k0 < K; k0 += 16) {
#pragma unroll
        for (int i = tid; i < 1024; i += 256) {
            int r = i >> 4, c = i & 15;
            int gr = row0 + r;
            As[c][r] = (gr < M) ? A[(size_t)gr * K + k0 + c] : 0.f;
            Bs[c][r] = B[(size_t)(col0 + r) * ldb + k0 + c];
        }
        __syncthreads();
#pragma unroll
        for (int k = 0; k < 16; k++) {
            float a[4], b[4];
#pragma unroll
            for (int i = 0; i < 4; i++) a[i] = As[k][ty * 4 + i];
#pragma unroll
            for (int j = 0; j < 4; j++) b[j] = Bs[k][tx * 4 + j];
#pragma unroll
            for (int i = 0; i < 4; i++)
#pragma unroll
                for (int j = 0; j < 4; j++) acc[i][j] += a[i] * b[j];
        }
        __syncthreads();
    }
#pragma unroll
    for (int i = 0; i < 4; i++) {
        int gr = row0 + ty * 4 + i;
        if (gr >= M) continue;
#pragma unroll
        for (int j = 0; j < 4; j++) {
            int gc = col0 + tx * 4 + j;
            float v = acc[i][j];
            if (bias) v += bias[gc];
            if (act == 1) v = v > 0.f ? v : 0.01f * v;
            C[(size_t)gr * N + gc] = v;
        }
    }
}

// ---------------- fill ----------------
__global__ void fill_kernel(float* p, float v, int n) {
    int i = blockIdx.x * blockDim.x + threadIdx.x;
    if (i < n) p[i] = v;
}

// ---------------- GATEConv per-node attention scalars ----------------
// tmp = x0 @ W1[:, :H]^T (no bias). a_src[n] = lrelu(tmp + b1) . att_l ; a_dst[n] = x0 . att_r
__global__ void gate_node_atts(const float* __restrict__ tmp, const float* __restrict__ W1,
                               const float* __restrict__ att_l, const float* __restrict__ x0,
                               const float* __restrict__ att_r, float* __restrict__ asrc,
                               float* __restrict__ adst, int n_rows) {
    int w = (blockIdx.x * blockDim.x + threadIdx.x) >> 5;
    int lane = threadIdx.x & 31;
    if (w >= n_rows) return;
    float4 tv = ((const float4*)(tmp + (size_t)w * HH))[lane];
    float4 xv = ((const float4*)(x0 + (size_t)w * HH))[lane];
    float s1 = 0.f, s2 = 0.f;
    const float* t = &tv.x;
    const float* xp = &xv.x;
#pragma unroll
    for (int j = 0; j < 4; j++) {
        int k = lane * 4 + j;
        float xe = t[j] + W1[(size_t)k * (HH + 1) + HH];
        xe = xe > 0.f ? xe : 0.01f * xe;
        s1 += xe * att_l[k];
        s2 += xp[j] * att_r[k];
    }
    s1 = warp_sum(s1);
    s2 = warp_sum(s2);
    if (lane == 0) { asrc[w] = s1; adst[w] = s2; }
}

// ---------------- per-node dots ----------------
__global__ void node_two_dots(const float* __restrict__ xw, const float* __restrict__ v1,
                              const float* __restrict__ v2, float* __restrict__ o1,
                              float* __restrict__ o2, int n_rows) {
    int w = (blockIdx.x * blockDim.x + threadIdx.x) >> 5;
    int lane = threadIdx.x & 31;
    if (w >= n_rows) return;
    float4 xv = ((const float4*)(xw + (size_t)w * HH))[lane];
    const float* xp = &xv.x;
    float s1 = 0.f, s2 = 0.f;
#pragma unroll
    for (int j = 0; j < 4; j++) {
        int k = lane * 4 + j;
        s1 += xp[j] * v1[k];
        s2 += xp[j] * v2[k];
    }
    s1 = warp_sum(s1);
    s2 = warp_sum(s2);
    if (lane == 0) { o1[w] = s1; o2[w] = s2; }
}

__global__ void node_one_dot(const float* __restrict__ xw, const float* __restrict__ v1,
                             float* __restrict__ o1, int n_rows) {
    int w = (blockIdx.x * blockDim.x + threadIdx.x) >> 5;
    int lane = threadIdx.x & 31;
    if (w >= n_rows) return;
    float4 xv = ((const float4*)(xw + (size_t)w * HH))[lane];
    const float* xp = &xv.x;
    float s1 = 0.f;
#pragma unroll
    for (int j = 0; j < 4; j++) s1 += xp[j] * v1[lane * 4 + j];
    s1 = warp_sum(s1);
    if (lane == 0) o1[w] = s1;
}

// ---------------- edge passes ----------------
__global__ void edge_logits(const int* __restrict__ src, const int* __restrict__ dst,
                            const float* __restrict__ asrc, const float* __restrict__ adst,
                            float* __restrict__ logit, float* __restrict__ segmax, int n_e) {
    int e = blockIdx.x * blockDim.x + threadIdx.x;
    if (e >= n_e) return;
    int d = dst[e];
    float v = asrc[src[e]] + adst[d];
    v = v > 0.f ? v : 0.01f * v;
    logit[e] = v;
    atomicMaxFloat(&segmax[d], v);
}

__global__ void edge_accum(const int* __restrict__ src, const int* __restrict__ dst,
                           const float* __restrict__ logit, const float* __restrict__ segmax,
                           float* __restrict__ segsum, const float* __restrict__ xw,
                           float* __restrict__ hout, int n_e) {
    int e = (blockIdx.x * blockDim.x + threadIdx.x) >> 5;
    int lane = threadIdx.x & 31;
    if (e >= n_e) return;
    int s = src[e], d = dst[e];
    float ev;
    if (lane == 0) {
        ev = expf(logit[e] - segmax[d]);
        atomicAdd(&segsum[d], ev);
    }
    ev = __shfl_sync(0xffffffffu, ev, 0);
    float4 v = ((const float4*)(xw + (size_t)s * HH))[lane];
    float* ho = hout + (size_t)d * HH + lane * 4;
    atomicAdd(ho + 0, ev * v.x);
    atomicAdd(ho + 1, ev * v.y);
    atomicAdd(ho + 2, ev * v.z);
    atomicAdd(ho + 3, ev * v.w);
}

// ---------------- h = elu(h/(s+eps) + bias) ----------------
__global__ void norm_bias_elu(float* __restrict__ h, const float* __restrict__ segsum,
                              const float* __restrict__ bias, int rows) {
    int idx = blockIdx.x * blockDim.x + threadIdx.x;
    if (idx >= rows * HH) return;
    int r = idx / HH, c = idx - r * HH;
    float v = h[idx] / (segsum[r] + 1e-16f) + bias[c];
    h[idx] = v > 0.f ? v : (expf(v) - 1.f);
}

// ---------------- GRU combine + relu ----------------
__global__ void gru_combine(const float* __restrict__ gi, const float* __restrict__ gh,
                            const float* __restrict__ hprev, float* __restrict__ outp, int rows) {
    int idx = blockIdx.x * blockDim.x + threadIdx.x;
    if (idx >= rows * HH) return;
    int r = idx / HH, c = idx - r * HH;
    const float* gir = gi + (size_t)r * H3;
    const float* ghr = gh + (size_t)r * H3;
    float ir = gir[c], iz = gir[c + HH], in_ = gir[c + 2 * HH];
    float hr = ghr[c], hz = ghr[c + HH], hn = ghr[c + 2 * HH];
    float rr = 1.f / (1.f + expf(-(ir + hr)));
    float z = 1.f / (1.f + expf(-(iz + hz)));
    float n = tanhf(in_ + rr * hn);
    float o = (1.f - z) * n + z * hprev[idx];
    outp[idx] = o > 0.f ? o : 0.f;
}

// ---------------- mol readout ----------------
__global__ void scatter_nodes(const float* __restrict__ xc, const int* __restrict__ batch,
                              float* __restrict__ outG, int n_rows) {
    int w = (blockIdx.x * blockDim.x + threadIdx.x) >> 5;
    int lane = threadIdx.x & 31;
    if (w >= n_rows) return;
    int b = batch[w];
    float4 v = ((const float4*)(xc + (size_t)w * HH))[lane];
    float* o = outG + (size_t)b * HH + lane * 4;
    atomicAdd(o + 0, v.x);
    atomicAdd(o + 1, v.y);
    atomicAdd(o + 2, v.z);
    atomicAdd(o + 3, v.w);
}

__global__ void relu_ip(float* p, int n) {
    int i = blockIdx.x * blockDim.x + threadIdx.x;
    if (i < n) p[i] = p[i] > 0.f ? p[i] : 0.f;
}

// vvec[k] = sum_j mol_W[j,k] * att_dst[j]
__global__ void compute_vvec(const float* __restrict__ molW, const float* __restrict__ attdst,
                             float* __restrict__ v) {
    int k = threadIdx.x;
    float s = 0.f;
    for (int j = 0; j < HH; j++) s += molW[(size_t)j * HH + k] * attdst[j];
    v[k] = s;
}

__global__ void mol_logits(const float* __restrict__ asrcN, const float* __restrict__ adstG,
                           const int* __restrict__ batch, float* __restrict__ logit,
                           float* __restrict__ segmax, int n_rows) {
    int i = blockIdx.x * blockDim.x + threadIdx.x;
    if (i >= n_rows) return;
    int b = batch[i];
    float v = asrcN[i] + adstG[b];
    v = v > 0.f ? v : 0.01f * v;
    logit[i] = v;
    atomicMaxFloat(&segmax[b], v);
}

__global__ void mol_accum(const int* __restrict__ batch, const float* __restrict__ logit,
                          const float* __restrict__ segmax, float* __restrict__ segsum,
                          const float* __restrict__ xw, float* __restrict__ hG, int n_rows) {
    int i = (blockIdx.x * blockDim.x + threadIdx.x) >> 5;
    int lane = threadIdx.x & 31;
    if (i >= n_rows) return;
    int b = batch[i];
    float ev;
    if (lane == 0) {
        ev = expf(logit[i] - segmax[b]);
        atomicAdd(&segsum[b], ev);
    }
    ev = __shfl_sync(0xffffffffu, ev, 0);
    float4 v = ((const float4*)(xw + (size_t)i * HH))[lane];
    float* o = hG + (size_t)b * HH + lane * 4;
    atomicAdd(o + 0, ev * v.x);
    atomicAdd(o + 1, ev * v.y);
    atomicAdd(o + 2, ev * v.z);
    atomicAdd(o + 3, ev * v.w);
}

__global__ void final_out(const float* __restrict__ outG, const float* __restrict__ W,
                          const float* __restrict__ b, float* __restrict__ y, int g_rows) {
    int g = (blockIdx.x * blockDim.x + threadIdx.x) >> 5;
    int lane = threadIdx.x & 31;
    if (g >= g_rows) return;
    float4 v = ((const float4*)(outG + (size_t)g * HH))[lane];
    const float* vp = &v.x;
    float s = 0.f;
#pragma unroll
    for (int j = 0; j < 4; j++) s += vp[j] * W[lane * 4 + j];
    s = warp_sum(s);
    if (lane == 0) y[g] = s + b[0];
}

// ---------------- host ----------------
static inline int cdiv(int a, int b) { return (a + b - 1) / b; }

extern "C" void kernel_launch(void* const* d_in, const int* in_sizes, int n_in,
                              void* d_out, int out_size) {
    const float* x = (const float*)d_in[0];
    const int* ei = (const int*)d_in[1];
    const int* batch = (const int*)d_in[2];
    const float* lin1_W = (const float*)d_in[3];
    const float* lin1_b = (const float*)d_in[4];
    const float* gate_W1 = (const float*)d_in[5];
    const float* gate_W2 = (const float*)d_in[6];
    const float* gate_att_l = (const float*)d_in[7];
    const float* gate_att_r = (const float*)d_in[8];
    const float* gate_bias = (const float*)d_in[9];
    const float* gru0_Wi = (const float*)d_in[10];
    const float* gru0_bi = (const float*)d_in[11];
    const float* gru0_Wh = (const float*)d_in[12];
    const float* gru0_bh = (const float*)d_in[13];
    const float* atom_W = (const float*)d_in[14];
    const float* atom_att_src = (const float*)d_in[15];
    const float* atom_att_dst = (const float*)d_in[16];
    const float* atom_bias = (const float*)d_in[17];
    const float* atom_gru_Wi = (const float*)d_in[18];
    const float* atom_gru_bi = (const float*)d_in[19];
    const float* atom_gru_Wh = (const float*)d_in[20];
    const float* atom_gru_bh = (const float*)d_in[21];
    const float* mol_W = (const float*)d_in[22];
    const float* mol_att_src = (const float*)d_in[23];
    const float* mol_att_dst = (const float*)d_in[24];
    const float* mol_bias = (const float*)d_in[25];
    const float* mol_gru_Wi = (const float*)d_in[26];
    const float* mol_gru_bi = (const float*)d_in[27];
    const float* mol_gru_Wh = (const float*)d_in[28];
    const float* mol_gru_bh = (const float*)d_in[29];
    const float* lin2_W = (const float*)d_in[30];
    const float* lin2_b = (const float*)d_in[31];

    const int* src = ei;
    const int* dst = ei + EE;

    float *x0, *xw, *h, *xc, *gi, *gh, *asrc, *adst, *segmax, *segsum, *logit;
    float *outG, *hG, *giG, *ghG, *adstG, *segmaxG, *segsumG, *vvec;
    cudaGetSymbolAddress((void**)&x0, d_x0);
    cudaGetSymbolAddress((void**)&xw, d_xw);
    cudaGetSymbolAddress((void**)&h, d_h);
    cudaGetSymbolAddress((void**)&xc, d_xc);
    cudaGetSymbolAddress((void**)&gi, d_gi);
    cudaGetSymbolAddress((void**)&gh, d_gh);
    cudaGetSymbolAddress((void**)&asrc, d_asrc);
    cudaGetSymbolAddress((void**)&adst, d_adst);
    cudaGetSymbolAddress((void**)&segmax, d_segmax);
    cudaGetSymbolAddress((void**)&segsum, d_segsum);
    cudaGetSymbolAddress((void**)&logit, d_logit);
    cudaGetSymbolAddress((void**)&outG, d_outG);
    cudaGetSymbolAddress((void**)&hG, d_hG);
    cudaGetSymbolAddress((void**)&giG, d_giG);
    cudaGetSymbolAddress((void**)&ghG, d_ghG);
    cudaGetSymbolAddress((void**)&adstG, d_adstG);
    cudaGetSymbolAddress((void**)&segmaxG, d_segmaxG);
    cudaGetSymbolAddress((void**)&segsumG, d_segsumG);
    cudaGetSymbolAddress((void**)&vvec, d_vvec);

    const float NEG_INF = -INFINITY;
    dim3 g_n128(cdiv(HH, 64), cdiv(NN, 64));
    dim3 g_n384(cdiv(H3, 64), cdiv(NN, 64));
    dim3 g_g384(cdiv(H3, 64), cdiv(GG, 64));
    int wpb_n = cdiv(NN, 8);   // warp-per-node grids (256 threads = 8 warps)
    int wpb_e = cdiv(EE, 8);
    int wpb_g = cdiv(GG, 8);

    // x0 = lrelu(x @ lin1_W^T + b)
    sgemm<<<g_n128, 256>>>(x, lin1_W, lin1_b, x0, NN, HH, IN_CH, IN_CH, 1);

    // ---- GATEConv ----
    sgemm<<<g_n128, 256>>>(x0, gate_W1, nullptr, xw, NN, HH, HH, HH + 1, 0);
    gate_node_atts<<<wpb_n, 256>>>(xw, gate_W1, gate_att_l, x0, gate_att_r, asrc, adst, NN);
    sgemm<<<g_n128, 256>>>(x0, gate_W2, nullptr, xw, NN, HH, HH, HH, 0);
    fill_kernel<<<cdiv(NN, 256), 256>>>(segmax, NEG_INF, NN);
    fill_kernel<<<cdiv(NN, 256), 256>>>(segsum, 0.f, NN);
    fill_kernel<<<cdiv(NN * HH, 256), 256>>>(h, 0.f, NN * HH);
    edge_logits<<<cdiv(EE, 256), 256>>>(src, dst, asrc, adst, logit, segmax, EE);
    edge_accum<<<wpb_e, 256>>>(src, dst, logit, segmax, segsum, xw, h, EE);
    norm_bias_elu<<<cdiv(NN * HH, 256), 256>>>(h, segsum, gate_bias, NN);
    sgemm<<<g_n384, 256>>>(h, gru0_Wi, gru0_bi, gi, NN, H3, HH, HH, 0);
    sgemm<<<g_n384, 256>>>(x0, gru0_Wh, gru0_bh, gh, NN, H3, HH, HH, 0);
    gru_combine<<<cdiv(NN * HH, 256), 256>>>(gi, gh, x0, xc, NN);

    // ---- extra atom GAT + GRU layers ----
    for (int l = 0; l < 2; l++) {
        sgemm<<<g_n128, 256>>>(xc, atom_W + (size_t)l * HH * HH, nullptr, xw, NN, HH, HH, HH, 0);
        node_two_dots<<<wpb_n, 256>>>(xw, atom_att_src + l * HH, atom_att_dst + l * HH, asrc, adst, NN);
        fill_kernel<<<cdiv(NN, 256), 256>>>(segmax, NEG_INF, NN);
        fill_kernel<<<cdiv(NN, 256), 256>>>(segsum, 0.f, NN);
        fill_kernel<<<cdiv(NN * HH, 256), 256>>>(h, 0.f, NN * HH);
        edge_logits<<<cdiv(EE, 256), 256>>>(src, dst, asrc, adst, logit, segmax, EE);
        edge_accum<<<wpb_e, 256>>>(src, dst, logit, segmax, segsum, xw, h, EE);
        norm_bias_elu<<<cdiv(NN * HH, 256), 256>>>(h, segsum, atom_bias + l * HH, NN);
        sgemm<<<g_n384, 256>>>(h, atom_gru_Wi + (size_t)l * H3 * HH, atom_gru_bi + l * H3, gi, NN, H3, HH, HH, 0);
        sgemm<<<g_n384, 256>>>(xc, atom_gru_Wh + (size_t)l * H3 * HH, atom_gru_bh + l * H3, gh, NN, H3, HH, HH, 0);
        gru_combine<<<cdiv(NN * HH, 256), 256>>>(gi, gh, xc, xc, NN);
    }

    // ---- molecule readout ----
    fill_kernel<<<cdiv(GG * HH, 256), 256>>>(outG, 0.f, GG * HH);
    scatter_nodes<<<wpb_n, 256>>>(xc, batch, outG, NN);
    relu_ip<<<cdiv(GG * HH, 256), 256>>>(outG, GG * HH);
    sgemm<<<g_n128, 256>>>(xc, mol_W, nullptr, xw, NN, HH, HH, HH, 0);
    node_one_dot<<<wpb_n, 256>>>(xw, mol_att_src, asrc, NN);
    compute_vvec<<<1, HH>>>(mol_W, mol_att_dst, vvec);

    for (int t = 0; t < 2; t++) {
        node_one_dot<<<wpb_g, 256>>>(outG, vvec, adstG, GG);
        fill_kernel<<<cdiv(GG, 256), 256>>>(segmaxG, NEG_INF, GG);
        fill_kernel<<<cdiv(GG, 256), 256>>>(segsumG, 0.f, GG);
        fill_kernel<<<cdiv(GG * HH, 256), 256>>>(hG, 0.f, GG * HH);
        mol_logits<<<cdiv(NN, 256), 256>>>(asrc, adstG, batch, logit, segmaxG, NN);
        mol_accum<<<wpb_n, 256>>>(batch, logit, segmaxG, segsumG, xw, hG, NN);
        norm_bias_elu<<<cdiv(GG * HH, 256), 256>>>(hG, segsumG, mol_bias, GG);
        sgemm<<<g_g384, 256>>>(hG, mol_gru_Wi, mol_gru_bi, giG, GG, H3, HH, HH, 0);
        sgemm<<<g_g384, 256>>>(outG, mol_gru_Wh, mol_gru_bh, ghG, GG, H3, HH, HH, 0);
        gru_combine<<<cdiv(GG * HH, 256), 256>>>(giG, ghG, outG, outG, GG);
    }

    final_out<<<wpb_g, 256>>>(outG, lin2_W, lin2_b, (float*)d_out, GG);
}

// round 2
// speedup vs baseline: 1.4011x; 1.4011x over previous
#include <cuda_runtime.h>
#include <math.h>
#include <stdint.h>

#define NN 100000
#define EE 1600000
#define IN_CH 64
#define HH 128
#define H3 384
#define GG 4096

// ---------------- scratch (no allocations allowed) ----------------
__device__ float d_x0[NN * HH];
__device__ float d_xw[NN * HH];
__device__ float d_h[NN * HH];
__device__ float d_xc[NN * HH];
__device__ float d_gi[NN * H3];
__device__ float d_gh[NN * H3];
__device__ float d_asrc[NN];
__device__ float d_adst[NN];
__device__ float d_segmax[NN];
__device__ float d_segsum[NN];
__device__ float d_logit[EE];
__device__ float d_outG[GG * HH];
__device__ float d_hG[GG * HH];
__device__ float d_giG[GG * H3];
__device__ float d_ghG[GG * H3];
__device__ float d_adstG[GG];
__device__ float d_segmaxG[GG];
__device__ float d_segsumG[GG];
__device__ float d_vvec[HH];

// ---------------- helpers ----------------
__device__ __forceinline__ float warp_sum(float v) {
#pragma unroll
    for (int o = 16; o > 0; o >>= 1) v += __shfl_down_sync(0xffffffffu, v, o);
    return v;
}

__device__ __forceinline__ void atomicMaxFloat(float* addr, float v) {
    if (v >= 0.f)
        atomicMax((int*)addr, __float_as_int(v));
    else
        atomicMin((unsigned int*)addr, __float_as_uint(v));
}

__device__ __forceinline__ uint32_t f2tf32(float f) {
    uint32_t o;
    asm("cvt.rna.tf32.f32 %0, %1;" : "=r"(o) : "f"(f));
    return o;
}

__device__ __forceinline__ void mma_tf32(float* c, const uint32_t* a, const uint32_t* b) {
    asm volatile(
        "mma.sync.aligned.m16n8k8.row.col.f32.tf32.tf32.f32 "
        "{%0,%1,%2,%3}, {%4,%5,%6,%7}, {%8,%9}, {%0,%1,%2,%3};"
        : "+f"(c[0]), "+f"(c[1]), "+f"(c[2]), "+f"(c[3])
        : "r"(a[0]), "r"(a[1]), "r"(a[2]), "r"(a[3]), "r"(b[0]), "r"(b[1]));
}

// ---------------- tensor-core fp32 GEMM (3xTF32 split) ----------------
// C[M,N] = A[M,K] @ B[N,K]^T (+bias, act). N % 128 == 0, K % 16 == 0.
// act: 0 = none, 1 = leaky_relu(0.01)
__global__ void __launch_bounds__(256) sgemm(const float* __restrict__ A,
                                             const float* __restrict__ B,
                                             const float* __restrict__ bias,
                                             float* __restrict__ C,
                                             int M, int N, int K, int ldb, int act) {
    __shared__ uint32_t Ah[16][132];
    __shared__ uint32_t Al[16][132];
    __shared__ uint32_t Bh[16][132];
    __shared__ uint32_t Bl[16][132];

    const int tid = threadIdx.x;
    const int lane = tid & 31;
    const int warp = tid >> 5;
    const int g = lane >> 2;   // group id 0..7
    const int t = lane & 3;    // thread in group 0..3
    const int wrow = (warp & 1) * 64;
    const int wcol = (warp >> 1) * 32;
    const int row0 = blockIdx.y * 128;
    const int col0 = blockIdx.x * 128;

    float acc[4][4][4];
#pragma unroll
    for (int mt = 0; mt < 4; mt++)
#pragma unroll
        for (int nt = 0; nt < 4; nt++)
#pragma unroll
            for (int i = 0; i < 4; i++) acc[mt][nt][i] = 0.f;

    const bool b_vec = ((ldb & 3) == 0);

    for (int k0 = 0; k0 < K; k0 += 16) {
        __syncthreads();
#pragma unroll
        for (int it = 0; it < 2; it++) {
            int idx = tid * 2 + it;      // 0..511
            int r = idx >> 2;            // 0..127
            int kg = (idx & 3) << 2;     // 0,4,8,12
            float av[4];
            int ar = row0 + r;
            if (ar < M) {
                float4 v = *(const float4*)(A + (size_t)ar * K + k0 + kg);
                av[0] = v.x; av[1] = v.y; av[2] = v.z; av[3] = v.w;
            } else {
                av[0] = av[1] = av[2] = av[3] = 0.f;
            }
            float bv[4];
            const float* bp = B + (size_t)(col0 + r) * ldb + k0 + kg;
            if (b_vec) {
                float4 v = *(const float4*)bp;
                bv[0] = v.x; bv[1] = v.y; bv[2] = v.z; bv[3] = v.w;
            } else {
#pragma unroll
                for (int j = 0; j < 4; j++) bv[j] = bp[j];
            }
#pragma unroll
            for (int j = 0; j < 4; j++) {
                uint32_t hi = f2tf32(av[j]);
                Ah[kg + j][r] = hi;
                Al[kg + j][r] = f2tf32(av[j] - __uint_as_float(hi));
                uint32_t bh = f2tf32(bv[j]);
                Bh[kg + j][r] = bh;
                Bl[kg + j][r] = f2tf32(bv[j] - __uint_as_float(bh));
            }
        }
        __syncthreads();
#pragma unroll
        for (int kk = 0; kk < 2; kk++) {
            const int k8 = kk * 8;
            uint32_t ahi[4][4], alo[4][4];
#pragma unroll
            for (int mt = 0; mt < 4; mt++) {
                int r = wrow + mt * 16 + g;
                ahi[mt][0] = Ah[k8 + t][r];
                ahi[mt][1] = Ah[k8 + t][r + 8];
                ahi[mt][2] = Ah[k8 + t + 4][r];
                ahi[mt][3] = Ah[k8 + t + 4][r + 8];
                alo[mt][0] = Al[k8 + t][r];
                alo[mt][1] = Al[k8 + t][r + 8];
                alo[mt][2] = Al[k8 + t + 4][r];
                alo[mt][3] = Al[k8 + t + 4][r + 8];
            }
            uint32_t bhi[4][2], blo[4][2];
#pragma unroll
            for (int nt = 0; nt < 4; nt++) {
                int c = wcol + nt * 8 + g;
                bhi[nt][0] = Bh[k8 + t][c];
                bhi[nt][1] = Bh[k8 + t + 4][c];
                blo[nt][0] = Bl[k8 + t][c];
                blo[nt][1] = Bl[k8 + t + 4][c];
            }
#pragma unroll
            for (int mt = 0; mt < 4; mt++)
#pragma unroll
                for (int nt = 0; nt < 4; nt++) {
                    mma_tf32(acc[mt][nt], alo[mt], bhi[nt]);
                    mma_tf32(acc[mt][nt], ahi[mt], blo[nt]);
                    mma_tf32(acc[mt][nt], ahi[mt], bhi[nt]);
                }
        }
    }

    // epilogue
#pragma unroll
    for (int mt = 0; mt < 4; mt++) {
#pragma unroll
        for (int nt = 0; nt < 4; nt++) {
            int r0 = row0 + wrow + mt * 16 + g;
            int c = col0 + wcol + nt * 8 + 2 * t;
            float b0 = bias ? bias[c] : 0.f;
            float b1 = bias ? bias[c + 1] : 0.f;
            float v00 = acc[mt][nt][0] + b0, v01 = acc[mt][nt][1] + b1;
            float v10 = acc[mt][nt][2] + b0, v11 = acc[mt][nt][3] + b1;
            if (act == 1) {
                v00 = v00 > 0.f ? v00 : 0.01f * v00;
                v01 = v01 > 0.f ? v01 : 0.01f * v01;
                v10 = v10 > 0.f ? v10 : 0.01f * v10;
                v11 = v11 > 0.f ? v11 : 0.01f * v11;
            }
            if (r0 < M) {
                C[(size_t)r0 * N + c] = v00;
                C[(size_t)r0 * N + c + 1] = v01;
            }
            if (r0 + 8 < M) {
                C[(size_t)(r0 + 8) * N + c] = v10;
                C[(size_t)(r0 + 8) * N + c + 1] = v11;
            }
        }
    }
}

// ---------------- fill ----------------
__global__ void fill_kernel(float* p, float v, int n) {
    int i = blockIdx.x * blockDim.x + threadIdx.x;
    if (i < n) p[i] = v;
}

// ---------------- GATEConv per-node attention scalars ----------------
__global__ void gate_node_atts(const float* __restrict__ tmp, const float* __restrict__ W1,
                               const float* __restrict__ att_l, const float* __restrict__ x0,
                               const float* __restrict__ att_r, float* __restrict__ asrc,
                               float* __restrict__ adst, int n_rows) {
    int w = (blockIdx.x * blockDim.x + threadIdx.x) >> 5;
    int lane = threadIdx.x & 31;
    if (w >= n_rows) return;
    float4 tv = ((const float4*)(tmp + (size_t)w * HH))[lane];
    float4 xv = ((const float4*)(x0 + (size_t)w * HH))[lane];
    float s1 = 0.f, s2 = 0.f;
    const float* t = &tv.x;
    const float* xp = &xv.x;
#pragma unroll
    for (int j = 0; j < 4; j++) {
        int k = lane * 4 + j;
        float xe = t[j] + W1[(size_t)k * (HH + 1) + HH];
        xe = xe > 0.f ? xe : 0.01f * xe;
        s1 += xe * att_l[k];
        s2 += xp[j] * att_r[k];
    }
    s1 = warp_sum(s1);
    s2 = warp_sum(s2);
    if (lane == 0) { asrc[w] = s1; adst[w] = s2; }
}

// ---------------- per-node dots ----------------
__global__ void node_two_dots(const float* __restrict__ xw, const float* __restrict__ v1,
                              const float* __restrict__ v2, float* __restrict__ o1,
                              float* __restrict__ o2, int n_rows) {
    int w = (blockIdx.x * blockDim.x + threadIdx.x) >> 5;
    int lane = threadIdx.x & 31;
    if (w >= n_rows) return;
    float4 xv = ((const float4*)(xw + (size_t)w * HH))[lane];
    const float* xp = &xv.x;
    float s1 = 0.f, s2 = 0.f;
#pragma unroll
    for (int j = 0; j < 4; j++) {
        int k = lane * 4 + j;
        s1 += xp[j] * v1[k];
        s2 += xp[j] * v2[k];
    }
    s1 = warp_sum(s1);
    s2 = warp_sum(s2);
    if (lane == 0) { o1[w] = s1; o2[w] = s2; }
}

__global__ void node_one_dot(const float* __restrict__ xw, const float* __restrict__ v1,
                             float* __restrict__ o1, int n_rows) {
    int w = (blockIdx.x * blockDim.x + threadIdx.x) >> 5;
    int lane = threadIdx.x & 31;
    if (w >= n_rows) return;
    float4 xv = ((const float4*)(xw + (size_t)w * HH))[lane];
    const float* xp = &xv.x;
    float s1 = 0.f;
#pragma unroll
    for (int j = 0; j < 4; j++) s1 += xp[j] * v1[lane * 4 + j];
    s1 = warp_sum(s1);
    if (lane == 0) o1[w] = s1;
}

// ---------------- edge passes ----------------
__global__ void edge_logits(const int* __restrict__ src, const int* __restrict__ dst,
                            const float* __restrict__ asrc, const float* __restrict__ adst,
                            float* __restrict__ logit, float* __restrict__ segmax, int n_e) {
    int e = blockIdx.x * blockDim.x + threadIdx.x;
    if (e >= n_e) return;
    int d = dst[e];
    float v = asrc[src[e]] + adst[d];
    v = v > 0.f ? v : 0.01f * v;
    logit[e] = v;
    atomicMaxFloat(&segmax[d], v);
}

__global__ void edge_accum(const int* __restrict__ src, const int* __restrict__ dst,
                           const float* __restrict__ logit, const float* __restrict__ segmax,
                           float* __restrict__ segsum, const float* __restrict__ xw,
                           float* __restrict__ hout, int n_e) {
    int e = (blockIdx.x * blockDim.x + threadIdx.x) >> 5;
    int lane = threadIdx.x & 31;
    if (e >= n_e) return;
    int s = src[e], d = dst[e];
    float ev;
    if (lane == 0) {
        ev = expf(logit[e] - segmax[d]);
        atomicAdd(&segsum[d], ev);
    }
    ev = __shfl_sync(0xffffffffu, ev, 0);
    float4 v = ((const float4*)(xw + (size_t)s * HH))[lane];
    float* ho = hout + (size_t)d * HH + lane * 4;
    atomicAdd(ho + 0, ev * v.x);
    atomicAdd(ho + 1, ev * v.y);
    atomicAdd(ho + 2, ev * v.z);
    atomicAdd(ho + 3, ev * v.w);
}

// ---------------- h = elu(h/(s+eps) + bias) ----------------
__global__ void norm_bias_elu(float* __restrict__ h, const float* __restrict__ segsum,
                              const float* __restrict__ bias, int rows) {
    int idx = blockIdx.x * blockDim.x + threadIdx.x;
    if (idx >= rows * HH) return;
    int r = idx / HH, c = idx - r * HH;
    float v = h[idx] / (segsum[r] + 1e-16f) + bias[c];
    h[idx] = v > 0.f ? v : (expf(v) - 1.f);
}

// ---------------- GRU combine + relu ----------------
__global__ void gru_combine(const float* __restrict__ gi, const float* __restrict__ gh,
                            const float* __restrict__ hprev, float* __restrict__ outp, int rows) {
    int idx = blockIdx.x * blockDim.x + threadIdx.x;
    if (idx >= rows * HH) return;
    int r = idx / HH, c = idx - r * HH;
    const float* gir = gi + (size_t)r * H3;
    const float* ghr = gh + (size_t)r * H3;
    float ir = gir[c], iz = gir[c + HH], in_ = gir[c + 2 * HH];
    float hr = ghr[c], hz = ghr[c + HH], hn = ghr[c + 2 * HH];
    float rr = 1.f / (1.f + expf(-(ir + hr)));
    float z = 1.f / (1.f + expf(-(iz + hz)));
    float n = tanhf(in_ + rr * hn);
    float o = (1.f - z) * n + z * hprev[idx];
    outp[idx] = o > 0.f ? o : 0.f;
}

// ---------------- mol readout ----------------
__global__ void scatter_nodes(const float* __restrict__ xc, const int* __restrict__ batch,
                              float* __restrict__ outG, int n_rows) {
    int w = (blockIdx.x * blockDim.x + threadIdx.x) >> 5;
    int lane = threadIdx.x & 31;
    if (w >= n_rows) return;
    int b = batch[w];
    float4 v = ((const float4*)(xc + (size_t)w * HH))[lane];
    float* o = outG + (size_t)b * HH + lane * 4;
    atomicAdd(o + 0, v.x);
    atomicAdd(o + 1, v.y);
    atomicAdd(o + 2, v.z);
    atomicAdd(o + 3, v.w);
}

__global__ void relu_ip(float* p, int n) {
    int i = blockIdx.x * blockDim.x + threadIdx.x;
    if (i < n) p[i] = p[i] > 0.f ? p[i] : 0.f;
}

__global__ void compute_vvec(const float* __restrict__ molW, const float* __restrict__ attdst,
                             float* __restrict__ v) {
    int k = threadIdx.x;
    float s = 0.f;
    for (int j = 0; j < HH; j++) s += molW[(size_t)j * HH + k] * attdst[j];
    v[k] = s;
}

__global__ void mol_logits(const float* __restrict__ asrcN, const float* __restrict__ adstG,
                           const int* __restrict__ batch, float* __restrict__ logit,
                           float* __restrict__ segmax, int n_rows) {
    int i = blockIdx.x * blockDim.x + threadIdx.x;
    if (i >= n_rows) return;
    int b = batch[i];
    float v = asrcN[i] + adstG[b];
    v = v > 0.f ? v : 0.01f * v;
    logit[i] = v;
    atomicMaxFloat(&segmax[b], v);
}

__global__ void mol_accum(const int* __restrict__ batch, const float* __restrict__ logit,
                          const float* __restrict__ segmax, float* __restrict__ segsum,
                          const float* __restrict__ xw, float* __restrict__ hG, int n_rows) {
    int i = (blockIdx.x * blockDim.x + threadIdx.x) >> 5;
    int lane = threadIdx.x & 31;
    if (i >= n_rows) return;
    int b = batch[i];
    float ev;
    if (lane == 0) {
        ev = expf(logit[i] - segmax[b]);
        atomicAdd(&segsum[b], ev);
    }
    ev = __shfl_sync(0xffffffffu, ev, 0);
    float4 v = ((const float4*)(xw + (size_t)i * HH))[lane];
    float* o = hG + (size_t)b * HH + lane * 4;
    atomicAdd(o + 0, ev * v.x);
    atomicAdd(o + 1, ev * v.y);
    atomicAdd(o + 2, ev * v.z);
    atomicAdd(o + 3, ev * v.w);
}

__global__ void final_out(const float* __restrict__ outG, const float* __restrict__ W,
                          const float* __restrict__ b, float* __restrict__ y, int g_rows) {
    int g = (blockIdx.x * blockDim.x + threadIdx.x) >> 5;
    int lane = threadIdx.x & 31;
    if (g >= g_rows) return;
    float4 v = ((const float4*)(outG + (size_t)g * HH))[lane];
    const float* vp = &v.x;
    float s = 0.f;
#pragma unroll
    for (int j = 0; j < 4; j++) s += vp[j] * W[lane * 4 + j];
    s = warp_sum(s);
    if (lane == 0) y[g] = s + b[0];
}

// ---------------- host ----------------
static inline int cdiv(int a, int b) { return (a + b - 1) / b; }

extern "C" void kernel_launch(void* const* d_in, const int* in_sizes, int n_in,
                              void* d_out, int out_size) {
    const float* x = (const float*)d_in[0];
    const int* ei = (const int*)d_in[1];
    const int* batch = (const int*)d_in[2];
    const float* lin1_W = (const float*)d_in[3];
    const float* lin1_b = (const float*)d_in[4];
    const float* gate_W1 = (const float*)d_in[5];
    const float* gate_W2 = (const float*)d_in[6];
    const float* gate_att_l = (const float*)d_in[7];
    const float* gate_att_r = (const float*)d_in[8];
    const float* gate_bias = (const float*)d_in[9];
    const float* gru0_Wi = (const float*)d_in[10];
    const float* gru0_bi = (const float*)d_in[11];
    const float* gru0_Wh = (const float*)d_in[12];
    const float* gru0_bh = (const float*)d_in[13];
    const float* atom_W = (const float*)d_in[14];
    const float* atom_att_src = (const float*)d_in[15];
    const float* atom_att_dst = (const float*)d_in[16];
    const float* atom_bias = (const float*)d_in[17];
    const float* atom_gru_Wi = (const float*)d_in[18];
    const float* atom_gru_bi = (const float*)d_in[19];
    const float* atom_gru_Wh = (const float*)d_in[20];
    const float* atom_gru_bh = (const float*)d_in[21];
    const float* mol_W = (const float*)d_in[22];
    const float* mol_att_src = (const float*)d_in[23];
    const float* mol_att_dst = (const float*)d_in[24];
    const float* mol_bias = (const float*)d_in[25];
    const float* mol_gru_Wi = (const float*)d_in[26];
    const float* mol_gru_bi = (const float*)d_in[27];
    const float* mol_gru_Wh = (const float*)d_in[28];
    const float* mol_gru_bh = (const float*)d_in[29];
    const float* lin2_W = (const float*)d_in[30];
    const float* lin2_b = (const float*)d_in[31];

    const int* src = ei;
    const int* dst = ei + EE;

    float *x0, *xw, *h, *xc, *gi, *gh, *asrc, *adst, *segmax, *segsum, *logit;
    float *outG, *hG, *giG, *ghG, *adstG, *segmaxG, *segsumG, *vvec;
    cudaGetSymbolAddress((void**)&x0, d_x0);
    cudaGetSymbolAddress((void**)&xw, d_xw);
    cudaGetSymbolAddress((void**)&h, d_h);
    cudaGetSymbolAddress((void**)&xc, d_xc);
    cudaGetSymbolAddress((void**)&gi, d_gi);
    cudaGetSymbolAddress((void**)&gh, d_gh);
    cudaGetSymbolAddress((void**)&asrc, d_asrc);
    cudaGetSymbolAddress((void**)&adst, d_adst);
    cudaGetSymbolAddress((void**)&segmax, d_segmax);
    cudaGetSymbolAddress((void**)&segsum, d_segsum);
    cudaGetSymbolAddress((void**)&logit, d_logit);
    cudaGetSymbolAddress((void**)&outG, d_outG);
    cudaGetSymbolAddress((void**)&hG, d_hG);
    cudaGetSymbolAddress((void**)&giG, d_giG);
    cudaGetSymbolAddress((void**)&ghG, d_ghG);
    cudaGetSymbolAddress((void**)&adstG, d_adstG);
    cudaGetSymbolAddress((void**)&segmaxG, d_segmaxG);
    cudaGetSymbolAddress((void**)&segsumG, d_segsumG);
    cudaGetSymbolAddress((void**)&vvec, d_vvec);

    const float NEG_INF = -INFINITY;
    dim3 g_n128(1, cdiv(NN, 128));
    dim3 g_n384(3, cdiv(NN, 128));
    dim3 g_g384(3, cdiv(GG, 128));
    int wpb_n = cdiv(NN, 8);   // warp-per-node grids (256 threads = 8 warps)
    int wpb_e = cdiv(EE, 8);
    int wpb_g = cdiv(GG, 8);

    // x0 = lrelu(x @ lin1_W^T + b)
    sgemm<<<g_n128, 256>>>(x, lin1_W, lin1_b, x0, NN, HH, IN_CH, IN_CH, 1);

    // ---- GATEConv ----
    sgemm<<<g_n128, 256>>>(x0, gate_W1, nullptr, xw, NN, HH, HH, HH + 1, 0);
    gate_node_atts<<<wpb_n, 256>>>(xw, gate_W1, gate_att_l, x0, gate_att_r, asrc, adst, NN);
    sgemm<<<g_n128, 256>>>(x0, gate_W2, nullptr, xw, NN, HH, HH, HH, 0);
    fill_kernel<<<cdiv(NN, 256), 256>>>(segmax, NEG_INF, NN);
    fill_kernel<<<cdiv(NN, 256), 256>>>(segsum, 0.f, NN);
    fill_kernel<<<cdiv(NN * HH, 256), 256>>>(h, 0.f, NN * HH);
    edge_logits<<<cdiv(EE, 256), 256>>>(src, dst, asrc, adst, logit, segmax, EE);
    edge_accum<<<wpb_e, 256>>>(src, dst, logit, segmax, segsum, xw, h, EE);
    norm_bias_elu<<<cdiv(NN * HH, 256), 256>>>(h, segsum, gate_bias, NN);
    sgemm<<<g_n384, 256>>>(h, gru0_Wi, gru0_bi, gi, NN, H3, HH, HH, 0);
    sgemm<<<g_n384, 256>>>(x0, gru0_Wh, gru0_bh, gh, NN, H3, HH, HH, 0);
    gru_combine<<<cdiv(NN * HH, 256), 256>>>(gi, gh, x0, xc, NN);

    // ---- extra atom GAT + GRU layers ----
    for (int l = 0; l < 2; l++) {
        sgemm<<<g_n128, 256>>>(xc, atom_W + (size_t)l * HH * HH, nullptr, xw, NN, HH, HH, HH, 0);
        node_two_dots<<<wpb_n, 256>>>(xw, atom_att_src + l * HH, atom_att_dst + l * HH, asrc, adst, NN);
        fill_kernel<<<cdiv(NN, 256), 256>>>(segmax, NEG_INF, NN);
        fill_kernel<<<cdiv(NN, 256), 256>>>(segsum, 0.f, NN);
        fill_kernel<<<cdiv(NN * HH, 256), 256>>>(h, 0.f, NN * HH);
        edge_logits<<<cdiv(EE, 256), 256>>>(src, dst, asrc, adst, logit, segmax, EE);
        edge_accum<<<wpb_e, 256>>>(src, dst, logit, segmax, segsum, xw, h, EE);
        norm_bias_elu<<<cdiv(NN * HH, 256), 256>>>(h, segsum, atom_bias + l * HH, NN);
        sgemm<<<g_n384, 256>>>(h, atom_gru_Wi + (size_t)l * H3 * HH, atom_gru_bi + l * H3, gi, NN, H3, HH, HH, 0);
        sgemm<<<g_n384, 256>>>(xc, atom_gru_Wh + (size_t)l * H3 * HH, atom_gru_bh + l * H3, gh, NN, H3, HH, HH, 0);
        gru_combine<<<cdiv(NN * HH, 256), 256>>>(gi, gh, xc, xc, NN);
    }

    // ---- molecule readout ----
    fill_kernel<<<cdiv(GG * HH, 256), 256>>>(outG, 0.f, GG * HH);
    scatter_nodes<<<wpb_n, 256>>>(xc, batch, outG, NN);
    relu_ip<<<cdiv(GG * HH, 256), 256>>>(outG, GG * HH);
    sgemm<<<g_n128, 256>>>(xc, mol_W, nullptr, xw, NN, HH, HH, HH, 0);
    node_one_dot<<<wpb_n, 256>>>(xw, mol_att_src, asrc, NN);
    compute_vvec<<<1, HH>>>(mol_W, mol_att_dst, vvec);

    for (int t = 0; t < 2; t++) {
        node_one_dot<<<wpb_g, 256>>>(outG, vvec, adstG, GG);
        fill_kernel<<<cdiv(GG, 256), 256>>>(segmaxG, NEG_INF, GG);
        fill_kernel<<<cdiv(GG, 256), 256>>>(segsumG, 0.f, GG);
        fill_kernel<<<cdiv(GG * HH, 256), 256>>>(hG, 0.f, GG * HH);
        mol_logits<<<cdiv(NN, 256), 256>>>(asrc, adstG, batch, logit, segmaxG, NN);
        mol_accum<<<wpb_n, 256>>>(batch, logit, segmaxG, segsumG, xw, hG, NN);
        norm_bias_elu<<<cdiv(GG * HH, 256), 256>>>(hG, segsumG, mol_bias, GG);
        sgemm<<<g_g384, 256>>>(hG, mol_gru_Wi, mol_gru_bi, giG, GG, H3, HH, HH, 0);
        sgemm<<<g_g384, 256>>>(outG, mol_gru_Wh, mol_gru_bh, ghG, GG, H3, HH, HH, 0);
        gru_combine<<<cdiv(GG * HH, 256), 256>>>(giG, ghG, outG, outG, GG);
    }

    final_out<<<wpb_g, 256>>>(outG, lin2_W, lin2_b, (float*)d_out, GG);
}

// round 3
// speedup vs baseline: 1.7456x; 1.2459x over previous
#include <cuda_runtime.h>
#include <math.h>
#include <stdint.h>

#define NN 100000
#define EE 1600000
#define IN_CH 64
#define HH 128
#define H3 384
#define GG 4096

// ---------------- scratch (no allocations allowed) ----------------
__device__ float d_x0[NN * HH];
__device__ float d_xw[NN * HH];
__device__ float d_h[NN * HH];
__device__ float d_xc[NN * HH];
__device__ float d_gi[NN * H3];
__device__ float d_gh[NN * H3];
__device__ float d_asrc[NN];
__device__ float d_adst[NN];
__device__ float d_segmax[NN];
__device__ float d_segsum[NN];
__device__ float d_logit[EE];
__device__ float d_outG[GG * HH];
__device__ float d_hG[GG * HH];
__device__ float d_giG[GG * H3];
__device__ float d_ghG[GG * H3];
__device__ float d_adstG[GG];
__device__ float d_segmaxG[GG];
__device__ float d_segsumG[GG];
__device__ float d_vvec[HH];

// ---------------- helpers ----------------
__device__ __forceinline__ float warp_sum(float v) {
#pragma unroll
    for (int o = 16; o > 0; o >>= 1) v += __shfl_down_sync(0xffffffffu, v, o);
    return v;
}

__device__ __forceinline__ void atomicMaxFloat(float* addr, float v) {
    if (v >= 0.f)
        atomicMax((int*)addr, __float_as_int(v));
    else
        atomicMin((unsigned int*)addr, __float_as_uint(v));
}

__device__ __forceinline__ uint32_t f2tf32(float f) {
    uint32_t o;
    asm("cvt.rna.tf32.f32 %0, %1;" : "=r"(o) : "f"(f));
    return o;
}

__device__ __forceinline__ void mma_tf32(float* c, const uint32_t* a, const uint32_t* b) {
    asm volatile(
        "mma.sync.aligned.m16n8k8.row.col.f32.tf32.tf32.f32 "
        "{%0,%1,%2,%3}, {%4,%5,%6,%7}, {%8,%9}, {%0,%1,%2,%3};"
        : "+f"(c[0]), "+f"(c[1]), "+f"(c[2]), "+f"(c[3])
        : "r"(a[0]), "r"(a[1]), "r"(a[2]), "r"(a[3]), "r"(b[0]), "r"(b[1]));
}

// vectorized fp32 reduction to global (sm_90+)
__device__ __forceinline__ void red_add4(float* p, float x, float y, float z, float w) {
    asm volatile("red.global.add.v4.f32 [%0], {%1,%2,%3,%4};"
                 :: "l"(p), "f"(x), "f"(y), "f"(z), "f"(w) : "memory");
}

// ---------------- tensor-core fp32 GEMM (3xTF32 split, hi/lo interleaved) ----------------
// C[M,N] = act(norm(A)[M,K] @ B[N,K]^T + bias)
// If nrm != null, A rows are transformed on the fly: a = elu(a/(nrm[row]+1e-16) + abias[k]).
// act: 0 = none, 1 = leaky_relu(0.01)
__global__ void __launch_bounds__(256) sgemm(const float* __restrict__ A,
                                             const float* __restrict__ B,
                                             const float* __restrict__ bias,
                                             float* __restrict__ C,
                                             int M, int N, int K, int ldb,
                                             const float* __restrict__ nrm,
                                             const float* __restrict__ abias,
                                             int act) {
    __shared__ uint2 A2[16][132];
    __shared__ uint2 B2[16][132];

    const int tid = threadIdx.x;
    const int lane = tid & 31;
    const int warp = tid >> 5;
    const int g = lane >> 2;   // group id 0..7
    const int t = lane & 3;    // thread in group 0..3
    const int wrow = (warp & 1) * 64;
    const int wcol = (warp >> 1) * 32;
    const int row0 = blockIdx.y * 128;
    const int col0 = blockIdx.x * 128;

    float acc[4][4][4];
#pragma unroll
    for (int mt = 0; mt < 4; mt++)
#pragma unroll
        for (int nt = 0; nt < 4; nt++)
#pragma unroll
            for (int i = 0; i < 4; i++) acc[mt][nt][i] = 0.f;

    const bool b_vec = ((ldb & 3) == 0);

    for (int k0 = 0; k0 < K; k0 += 16) {
        __syncthreads();
#pragma unroll
        for (int it = 0; it < 2; it++) {
            int idx = tid * 2 + it;      // 0..511
            int r = idx >> 2;            // 0..127
            int kg = (idx & 3) << 2;     // 0,4,8,12
            float av[4];
            int ar = row0 + r;
            if (ar < M) {
                float4 v = *(const float4*)(A + (size_t)ar * K + k0 + kg);
                av[0] = v.x; av[1] = v.y; av[2] = v.z; av[3] = v.w;
                if (nrm) {
                    float rinv = 1.f / (nrm[ar] + 1e-16f);
#pragma unroll
                    for (int j = 0; j < 4; j++) {
                        float u = av[j] * rinv + abias[k0 + kg + j];
                        av[j] = u > 0.f ? u : (expf(u) - 1.f);
                    }
                }
            } else {
                av[0] = av[1] = av[2] = av[3] = 0.f;
            }
            float bv[4];
            const float* bp = B + (size_t)(col0 + r) * ldb + k0 + kg;
            if (b_vec) {
                float4 v = *(const float4*)bp;
                bv[0] = v.x; bv[1] = v.y; bv[2] = v.z; bv[3] = v.w;
            } else {
#pragma unroll
                for (int j = 0; j < 4; j++) bv[j] = bp[j];
            }
#pragma unroll
            for (int j = 0; j < 4; j++) {
                uint32_t hi = f2tf32(av[j]);
                A2[kg + j][r] = make_uint2(hi, f2tf32(av[j] - __uint_as_float(hi)));
                uint32_t bh = f2tf32(bv[j]);
                B2[kg + j][r] = make_uint2(bh, f2tf32(bv[j] - __uint_as_float(bh)));
            }
        }
        __syncthreads();
#pragma unroll
        for (int kk = 0; kk < 2; kk++) {
            const int k8 = kk * 8;
            uint2 a2[4][4];
#pragma unroll
            for (int mt = 0; mt < 4; mt++) {
                int r = wrow + mt * 16 + g;
                a2[mt][0] = A2[k8 + t][r];
                a2[mt][1] = A2[k8 + t][r + 8];
                a2[mt][2] = A2[k8 + t + 4][r];
                a2[mt][3] = A2[k8 + t + 4][r + 8];
            }
            uint2 b2[4][2];
#pragma unroll
            for (int nt = 0; nt < 4; nt++) {
                int c = wcol + nt * 8 + g;
                b2[nt][0] = B2[k8 + t][c];
                b2[nt][1] = B2[k8 + t + 4][c];
            }
#pragma unroll
            for (int mt = 0; mt < 4; mt++) {
                uint32_t ahi[4] = {a2[mt][0].x, a2[mt][1].x, a2[mt][2].x, a2[mt][3].x};
                uint32_t alo[4] = {a2[mt][0].y, a2[mt][1].y, a2[mt][2].y, a2[mt][3].y};
#pragma unroll
                for (int nt = 0; nt < 4; nt++) {
                    uint32_t bhi[2] = {b2[nt][0].x, b2[nt][1].x};
                    uint32_t blo[2] = {b2[nt][0].y, b2[nt][1].y};
                    mma_tf32(acc[mt][nt], alo, bhi);
                    mma_tf32(acc[mt][nt], ahi, blo);
                    mma_tf32(acc[mt][nt], ahi, bhi);
                }
            }
        }
    }

    // epilogue
#pragma unroll
    for (int mt = 0; mt < 4; mt++) {
#pragma unroll
        for (int nt = 0; nt < 4; nt++) {
            int r0 = row0 + wrow + mt * 16 + g;
            int c = col0 + wcol + nt * 8 + 2 * t;
            float b0 = bias ? bias[c] : 0.f;
            float b1 = bias ? bias[c + 1] : 0.f;
            float v00 = acc[mt][nt][0] + b0, v01 = acc[mt][nt][1] + b1;
            float v10 = acc[mt][nt][2] + b0, v11 = acc[mt][nt][3] + b1;
            if (act == 1) {
                v00 = v00 > 0.f ? v00 : 0.01f * v00;
                v01 = v01 > 0.f ? v01 : 0.01f * v01;
                v10 = v10 > 0.f ? v10 : 0.01f * v10;
                v11 = v11 > 0.f ? v11 : 0.01f * v11;
            }
            if (r0 < M) {
                C[(size_t)r0 * N + c] = v00;
                C[(size_t)r0 * N + c + 1] = v01;
            }
            if (r0 + 8 < M) {
                C[(size_t)(r0 + 8) * N + c] = v10;
                C[(size_t)(r0 + 8) * N + c + 1] = v11;
            }
        }
    }
}

// ---------------- fill ----------------
__global__ void fill_kernel(float* p, float v, int n) {
    int i = blockIdx.x * blockDim.x + threadIdx.x;
    if (i < n) p[i] = v;
}

// ---------------- GATEConv per-node attention scalars ----------------
__global__ void gate_node_atts(const float* __restrict__ tmp, const float* __restrict__ W1,
                               const float* __restrict__ att_l, const float* __restrict__ x0,
                               const float* __restrict__ att_r, float* __restrict__ asrc,
                               float* __restrict__ adst, int n_rows) {
    int w = (blockIdx.x * blockDim.x + threadIdx.x) >> 5;
    int lane = threadIdx.x & 31;
    if (w >= n_rows) return;
    float4 tv = ((const float4*)(tmp + (size_t)w * HH))[lane];
    float4 xv = ((const float4*)(x0 + (size_t)w * HH))[lane];
    float s1 = 0.f, s2 = 0.f;
    const float* t = &tv.x;
    const float* xp = &xv.x;
#pragma unroll
    for (int j = 0; j < 4; j++) {
        int k = lane * 4 + j;
        float xe = t[j] + W1[(size_t)k * (HH + 1) + HH];
        xe = xe > 0.f ? xe : 0.01f * xe;
        s1 += xe * att_l[k];
        s2 += xp[j] * att_r[k];
    }
    s1 = warp_sum(s1);
    s2 = warp_sum(s2);
    if (lane == 0) { asrc[w] = s1; adst[w] = s2; }
}

// ---------------- per-node dots ----------------
__global__ void node_two_dots(const float* __restrict__ xw, const float* __restrict__ v1,
                              const float* __restrict__ v2, float* __restrict__ o1,
                              float* __restrict__ o2, int n_rows) {
    int w = (blockIdx.x * blockDim.x + threadIdx.x) >> 5;
    int lane = threadIdx.x & 31;
    if (w >= n_rows) return;
    float4 xv = ((const float4*)(xw + (size_t)w * HH))[lane];
    const float* xp = &xv.x;
    float s1 = 0.f, s2 = 0.f;
#pragma unroll
    for (int j = 0; j < 4; j++) {
        int k = lane * 4 + j;
        s1 += xp[j] * v1[k];
        s2 += xp[j] * v2[k];
    }
    s1 = warp_sum(s1);
    s2 = warp_sum(s2);
    if (lane == 0) { o1[w] = s1; o2[w] = s2; }
}

__global__ void node_one_dot(const float* __restrict__ xw, const float* __restrict__ v1,
                             float* __restrict__ o1, int n_rows) {
    int w = (blockIdx.x * blockDim.x + threadIdx.x) >> 5;
    int lane = threadIdx.x & 31;
    if (w >= n_rows) return;
    float4 xv = ((const float4*)(xw + (size_t)w * HH))[lane];
    const float* xp = &xv.x;
    float s1 = 0.f;
#pragma unroll
    for (int j = 0; j < 4; j++) s1 += xp[j] * v1[lane * 4 + j];
    s1 = warp_sum(s1);
    if (lane == 0) o1[w] = s1;
}

// ---------------- edge passes ----------------
__global__ void edge_logits(const int* __restrict__ src, const int* __restrict__ dst,
                            const float* __restrict__ asrc, const float* __restrict__ adst,
                            float* __restrict__ logit, float* __restrict__ segmax, int n_e) {
    int e = blockIdx.x * blockDim.x + threadIdx.x;
    if (e >= n_e) return;
    int d = dst[e];
    float v = asrc[src[e]] + adst[d];
    v = v > 0.f ? v : 0.01f * v;
    logit[e] = v;
    atomicMaxFloat(&segmax[d], v);
}

__global__ void edge_accum(const int* __restrict__ src, const int* __restrict__ dst,
                           const float* __restrict__ logit, const float* __restrict__ segmax,
                           float* __restrict__ segsum, const float* __restrict__ xw,
                           float* __restrict__ hout, int n_e) {
    int e = (blockIdx.x * blockDim.x + threadIdx.x) >> 5;
    int lane = threadIdx.x & 31;
    if (e >= n_e) return;
    int s = src[e], d = dst[e];
    float ev;
    if (lane == 0) {
        ev = expf(logit[e] - segmax[d]);
        atomicAdd(&segsum[d], ev);
    }
    ev = __shfl_sync(0xffffffffu, ev, 0);
    float4 v = ((const float4*)(xw + (size_t)s * HH))[lane];
    red_add4(hout + (size_t)d * HH + lane * 4, ev * v.x, ev * v.y, ev * v.z, ev * v.w);
}

// ---------------- GRU combine + relu ----------------
__global__ void gru_combine(const float* __restrict__ gi, const float* __restrict__ gh,
                            const float* __restrict__ hprev, float* __restrict__ outp, int rows) {
    int idx = blockIdx.x * blockDim.x + threadIdx.x;
    if (idx >= rows * HH) return;
    int r = idx / HH, c = idx - r * HH;
    const float* gir = gi + (size_t)r * H3;
    const float* ghr = gh + (size_t)r * H3;
    float ir = gir[c], iz = gir[c + HH], in_ = gir[c + 2 * HH];
    float hr = ghr[c], hz = ghr[c + HH], hn = ghr[c + 2 * HH];
    float rr = 1.f / (1.f + expf(-(ir + hr)));
    float z = 1.f / (1.f + expf(-(iz + hz)));
    float n = tanhf(in_ + rr * hn);
    float o = (1.f - z) * n + z * hprev[idx];
    outp[idx] = o > 0.f ? o : 0.f;
}

// ---------------- mol readout ----------------
__global__ void scatter_nodes(const float* __restrict__ xc, const int* __restrict__ batch,
                              float* __restrict__ outG, int n_rows) {
    int w = (blockIdx.x * blockDim.x + threadIdx.x) >> 5;
    int lane = threadIdx.x & 31;
    if (w >= n_rows) return;
    int b = batch[w];
    float4 v = ((const float4*)(xc + (size_t)w * HH))[lane];
    red_add4(outG + (size_t)b * HH + lane * 4, v.x, v.y, v.z, v.w);
}

__global__ void relu_ip(float* p, int n) {
    int i = blockIdx.x * blockDim.x + threadIdx.x;
    if (i < n) p[i] = p[i] > 0.f ? p[i] : 0.f;
}

__global__ void compute_vvec(const float* __restrict__ molW, const float* __restrict__ attdst,
                             float* __restrict__ v) {
    int k = threadIdx.x;
    float s = 0.f;
    for (int j = 0; j < HH; j++) s += molW[(size_t)j * HH + k] * attdst[j];
    v[k] = s;
}

__global__ void mol_logits(const float* __restrict__ asrcN, const float* __restrict__ adstG,
                           const int* __restrict__ batch, float* __restrict__ logit,
                           float* __restrict__ segmax, int n_rows) {
    int i = blockIdx.x * blockDim.x + threadIdx.x;
    if (i >= n_rows) return;
    int b = batch[i];
    float v = asrcN[i] + adstG[b];
    v = v > 0.f ? v : 0.01f * v;
    logit[i] = v;
    atomicMaxFloat(&segmax[b], v);
}

__global__ void mol_accum(const int* __restrict__ batch, const float* __restrict__ logit,
                          const float* __restrict__ segmax, float* __restrict__ segsum,
                          const float* __restrict__ xw, float* __restrict__ hG, int n_rows) {
    int i = (blockIdx.x * blockDim.x + threadIdx.x) >> 5;
    int lane = threadIdx.x & 31;
    if (i >= n_rows) return;
    int b = batch[i];
    float ev;
    if (lane == 0) {
        ev = expf(logit[i] - segmax[b]);
        atomicAdd(&segsum[b], ev);
    }
    ev = __shfl_sync(0xffffffffu, ev, 0);
    float4 v = ((const float4*)(xw + (size_t)i * HH))[lane];
    red_add4(hG + (size_t)b * HH + lane * 4, ev * v.x, ev * v.y, ev * v.z, ev * v.w);
}

__global__ void final_out(const float* __restrict__ outG, const float* __restrict__ W,
                          const float* __restrict__ b, float* __restrict__ y, int g_rows) {
    int g = (blockIdx.x * blockDim.x + threadIdx.x) >> 5;
    int lane = threadIdx.x & 31;
    if (g >= g_rows) return;
    float4 v = ((const float4*)(outG + (size_t)g * HH))[lane];
    const float* vp = &v.x;
    float s = 0.f;
#pragma unroll
    for (int j = 0; j < 4; j++) s += vp[j] * W[lane * 4 + j];
    s = warp_sum(s);
    if (lane == 0) y[g] = s + b[0];
}

// ---------------- host ----------------
static inline int cdiv(int a, int b) { return (a + b - 1) / b; }

extern "C" void kernel_launch(void* const* d_in, const int* in_sizes, int n_in,
                              void* d_out, int out_size) {
    const float* x = (const float*)d_in[0];
    const int* ei = (const int*)d_in[1];
    const int* batch = (const int*)d_in[2];
    const float* lin1_W = (const float*)d_in[3];
    const float* lin1_b = (const float*)d_in[4];
    const float* gate_W1 = (const float*)d_in[5];
    const float* gate_W2 = (const float*)d_in[6];
    const float* gate_att_l = (const float*)d_in[7];
    const float* gate_att_r = (const float*)d_in[8];
    const float* gate_bias = (const float*)d_in[9];
    const float* gru0_Wi = (const float*)d_in[10];
    const float* gru0_bi = (const float*)d_in[11];
    const float* gru0_Wh = (const float*)d_in[12];
    const float* gru0_bh = (const float*)d_in[13];
    const float* atom_W = (const float*)d_in[14];
    const float* atom_att_src = (const float*)d_in[15];
    const float* atom_att_dst = (const float*)d_in[16];
    const float* atom_bias = (const float*)d_in[17];
    const float* atom_gru_Wi = (const float*)d_in[18];
    const float* atom_gru_bi = (const float*)d_in[19];
    const float* atom_gru_Wh = (const float*)d_in[20];
    const float* atom_gru_bh = (const float*)d_in[21];
    const float* mol_W = (const float*)d_in[22];
    const float* mol_att_src = (const float*)d_in[23];
    const float* mol_att_dst = (const float*)d_in[24];
    const float* mol_bias = (const float*)d_in[25];
    const float* mol_gru_Wi = (const float*)d_in[26];
    const float* mol_gru_bi = (const float*)d_in[27];
    const float* mol_gru_Wh = (const float*)d_in[28];
    const float* mol_gru_bh = (const float*)d_in[29];
    const float* lin2_W = (const float*)d_in[30];
    const float* lin2_b = (const float*)d_in[31];

    const int* src = ei;
    const int* dst = ei + EE;

    float *x0, *xw, *h, *xc, *gi, *gh, *asrc, *adst, *segmax, *segsum, *logit;
    float *outG, *hG, *giG, *ghG, *adstG, *segmaxG, *segsumG, *vvec;
    cudaGetSymbolAddress((void**)&x0, d_x0);
    cudaGetSymbolAddress((void**)&xw, d_xw);
    cudaGetSymbolAddress((void**)&h, d_h);
    cudaGetSymbolAddress((void**)&xc, d_xc);
    cudaGetSymbolAddress((void**)&gi, d_gi);
    cudaGetSymbolAddress((void**)&gh, d_gh);
    cudaGetSymbolAddress((void**)&asrc, d_asrc);
    cudaGetSymbolAddress((void**)&adst, d_adst);
    cudaGetSymbolAddress((void**)&segmax, d_segmax);
    cudaGetSymbolAddress((void**)&segsum, d_segsum);
    cudaGetSymbolAddress((void**)&logit, d_logit);
    cudaGetSymbolAddress((void**)&outG, d_outG);
    cudaGetSymbolAddress((void**)&hG, d_hG);
    cudaGetSymbolAddress((void**)&giG, d_giG);
    cudaGetSymbolAddress((void**)&ghG, d_ghG);
    cudaGetSymbolAddress((void**)&adstG, d_adstG);
    cudaGetSymbolAddress((void**)&segmaxG, d_segmaxG);
    cudaGetSymbolAddress((void**)&segsumG, d_segsumG);
    cudaGetSymbolAddress((void**)&vvec, d_vvec);

    const float NEG_INF = -INFINITY;
    dim3 g_n128(1, cdiv(NN, 128));
    dim3 g_n384(3, cdiv(NN, 128));
    dim3 g_g384(3, cdiv(GG, 128));
    int wpb_n = cdiv(NN, 8);
    int wpb_e = cdiv(EE, 8);
    int wpb_g = cdiv(GG, 8);

    // x0 = lrelu(x @ lin1_W^T + b)
    sgemm<<<g_n128, 256>>>(x, lin1_W, lin1_b, x0, NN, HH, IN_CH, IN_CH, nullptr, nullptr, 1);

    // ---- GATEConv ----
    sgemm<<<g_n128, 256>>>(x0, gate_W1, nullptr, xw, NN, HH, HH, HH + 1, nullptr, nullptr, 0);
    gate_node_atts<<<wpb_n, 256>>>(xw, gate_W1, gate_att_l, x0, gate_att_r, asrc, adst, NN);
    sgemm<<<g_n128, 256>>>(x0, gate_W2, nullptr, xw, NN, HH, HH, HH, nullptr, nullptr, 0);
    fill_kernel<<<cdiv(NN, 256), 256>>>(segmax, NEG_INF, NN);
    cudaMemsetAsync(segsum, 0, NN * sizeof(float));
    cudaMemsetAsync(h, 0, (size_t)NN * HH * sizeof(float));
    edge_logits<<<cdiv(EE, 256), 256>>>(src, dst, asrc, adst, logit, segmax, EE);
    edge_accum<<<wpb_e, 256>>>(src, dst, logit, segmax, segsum, xw, h, EE);
    sgemm<<<g_n384, 256>>>(h, gru0_Wi, gru0_bi, gi, NN, H3, HH, HH, segsum, gate_bias, 0);
    sgemm<<<g_n384, 256>>>(x0, gru0_Wh, gru0_bh, gh, NN, H3, HH, HH, nullptr, nullptr, 0);
    gru_combine<<<cdiv(NN * HH, 256), 256>>>(gi, gh, x0, xc, NN);

    // ---- extra atom GAT + GRU layers ----
    for (int l = 0; l < 2; l++) {
        sgemm<<<g_n128, 256>>>(xc, atom_W + (size_t)l * HH * HH, nullptr, xw, NN, HH, HH, HH, nullptr, nullptr, 0);
        node_two_dots<<<wpb_n, 256>>>(xw, atom_att_src + l * HH, atom_att_dst + l * HH, asrc, adst, NN);
        fill_kernel<<<cdiv(NN, 256), 256>>>(segmax, NEG_INF, NN);
        cudaMemsetAsync(segsum, 0, NN * sizeof(float));
        cudaMemsetAsync(h, 0, (size_t)NN * HH * sizeof(float));
        edge_logits<<<cdiv(EE, 256), 256>>>(src, dst, asrc, adst, logit, segmax, EE);
        edge_accum<<<wpb_e, 256>>>(src, dst, logit, segmax, segsum, xw, h, EE);
        sgemm<<<g_n384, 256>>>(h, atom_gru_Wi + (size_t)l * H3 * HH, atom_gru_bi + l * H3, gi, NN, H3, HH, HH, segsum, atom_bias + l * HH, 0);
        sgemm<<<g_n384, 256>>>(xc, atom_gru_Wh + (size_t)l * H3 * HH, atom_gru_bh + l * H3, gh, NN, H3, HH, HH, nullptr, nullptr, 0);
        gru_combine<<<cdiv(NN * HH, 256), 256>>>(gi, gh, xc, xc, NN);
    }

    // ---- molecule readout ----
    cudaMemsetAsync(outG, 0, (size_t)GG * HH * sizeof(float));
    scatter_nodes<<<wpb_n, 256>>>(xc, batch, outG, NN);
    relu_ip<<<cdiv(GG * HH, 256), 256>>>(outG, GG * HH);
    sgemm<<<g_n128, 256>>>(xc, mol_W, nullptr, xw, NN, HH, HH, HH, nullptr, nullptr, 0);
    node_one_dot<<<wpb_n, 256>>>(xw, mol_att_src, asrc, NN);
    compute_vvec<<<1, HH>>>(mol_W, mol_att_dst, vvec);

    for (int t = 0; t < 2; t++) {
        node_one_dot<<<wpb_g, 256>>>(outG, vvec, adstG, GG);
        fill_kernel<<<cdiv(GG, 256), 256>>>(segmaxG, NEG_INF, GG);
        cudaMemsetAsync(segsumG, 0, GG * sizeof(float));
        cudaMemsetAsync(hG, 0, (size_t)GG * HH * sizeof(float));
        mol_logits<<<cdiv(NN, 256), 256>>>(asrc, adstG, batch, logit, segmaxG, NN);
        mol_accum<<<wpb_n, 256>>>(batch, logit, segmaxG, segsumG, xw, hG, NN);
        sgemm<<<g_g384, 256>>>(hG, mol_gru_Wi, mol_gru_bi, giG, GG, H3, HH, HH, segsumG, mol_bias, 0);
        sgemm<<<g_g384, 256>>>(outG, mol_gru_Wh, mol_gru_bh, ghG, GG, H3, HH, HH, nullptr, nullptr, 0);
        gru_combine<<<cdiv(GG * HH, 256), 256>>>(giG, ghG, outG, outG, GG);
    }

    final_out<<<wpb_g, 256>>>(outG, lin2_W, lin2_b, (float*)d_out, GG);
}

// round 4
// speedup vs baseline: 2.2023x; 1.2616x over previous
#include <cuda_runtime.h>
#include <math.h>
#include <stdint.h>

#define NN 100000
#define EE 1600000
#define IN_CH 64
#define HH 128
#define H3 384
#define GG 4096
#define FULL 0xffffffffu

// ---------------- scratch (no allocations allowed) ----------------
__device__ float d_x0[NN * HH];
__device__ float d_xw[NN * HH];
__device__ float d_h[NN * HH];
__device__ float d_xc[NN * HH];
__device__ float d_gi[NN * H3];
__device__ float d_gh[NN * H3];
__device__ float d_asrc[NN];
__device__ float d_adst[NN];
__device__ float d_outG[GG * HH];
__device__ float d_hG[GG * HH];
__device__ float d_giG[GG * H3];
__device__ float d_ghG[GG * H3];
__device__ float d_vvec[HH];
__device__ int d_deg[NN];
__device__ int d_ptr[NN + 1];
__device__ int d_cur[NN];
__device__ int d_csr_src[EE];
__device__ int d_bsum[128];
__device__ int d_gptr[GG + 1];

// ---------------- helpers ----------------
__device__ __forceinline__ float warp_sum_all(float v) {
#pragma unroll
    for (int o = 16; o > 0; o >>= 1) v += __shfl_xor_sync(FULL, v, o);
    return v;
}
__device__ __forceinline__ float warp_max_all(float v) {
#pragma unroll
    for (int o = 16; o > 0; o >>= 1) v = fmaxf(v, __shfl_xor_sync(FULL, v, o));
    return v;
}

__device__ __forceinline__ uint32_t f2tf32(float f) {
    uint32_t o;
    asm("cvt.rna.tf32.f32 %0, %1;" : "=r"(o) : "f"(f));
    return o;
}

__device__ __forceinline__ void mma_tf32(float* c, const uint32_t* a, const uint32_t* b) {
    asm volatile(
        "mma.sync.aligned.m16n8k8.row.col.f32.tf32.tf32.f32 "
        "{%0,%1,%2,%3}, {%4,%5,%6,%7}, {%8,%9}, {%0,%1,%2,%3};"
        : "+f"(c[0]), "+f"(c[1]), "+f"(c[2]), "+f"(c[3])
        : "r"(a[0]), "r"(a[1]), "r"(a[2]), "r"(a[3]), "r"(b[0]), "r"(b[1]));
}

// ---------------- tensor-core fp32 GEMM (3xTF32 split, hi/lo interleaved) ----------------
// C[M,N] = act(A[M,K] @ B[N,K]^T + bias). act: 0 = none, 1 = leaky_relu(0.01)
__global__ void __launch_bounds__(256) sgemm(const float* __restrict__ A,
                                             const float* __restrict__ B,
                                             const float* __restrict__ bias,
                                             float* __restrict__ C,
                                             int M, int N, int K, int ldb, int act) {
    __shared__ uint2 A2[16][132];
    __shared__ uint2 B2[16][132];

    const int tid = threadIdx.x;
    const int lane = tid & 31;
    const int warp = tid >> 5;
    const int g = lane >> 2;
    const int t = lane & 3;
    const int wrow = (warp & 1) * 64;
    const int wcol = (warp >> 1) * 32;
    const int row0 = blockIdx.y * 128;
    const int col0 = blockIdx.x * 128;

    float acc[4][4][4];
#pragma unroll
    for (int mt = 0; mt < 4; mt++)
#pragma unroll
        for (int nt = 0; nt < 4; nt++)
#pragma unroll
            for (int i = 0; i < 4; i++) acc[mt][nt][i] = 0.f;

    const bool b_vec = ((ldb & 3) == 0);

    for (int k0 = 0; k0 < K; k0 += 16) {
        __syncthreads();
#pragma unroll
        for (int it = 0; it < 2; it++) {
            int idx = tid * 2 + it;
            int r = idx >> 2;
            int kg = (idx & 3) << 2;
            float av[4];
            int ar = row0 + r;
            if (ar < M) {
                float4 v = *(const float4*)(A + (size_t)ar * K + k0 + kg);
                av[0] = v.x; av[1] = v.y; av[2] = v.z; av[3] = v.w;
            } else {
                av[0] = av[1] = av[2] = av[3] = 0.f;
            }
            float bv[4];
            const float* bp = B + (size_t)(col0 + r) * ldb + k0 + kg;
            if (b_vec) {
                float4 v = *(const float4*)bp;
                bv[0] = v.x; bv[1] = v.y; bv[2] = v.z; bv[3] = v.w;
            } else {
#pragma unroll
                for (int j = 0; j < 4; j++) bv[j] = bp[j];
            }
#pragma unroll
            for (int j = 0; j < 4; j++) {
                uint32_t hi = f2tf32(av[j]);
                A2[kg + j][r] = make_uint2(hi, f2tf32(av[j] - __uint_as_float(hi)));
                uint32_t bh = f2tf32(bv[j]);
                B2[kg + j][r] = make_uint2(bh, f2tf32(bv[j] - __uint_as_float(bh)));
            }
        }
        __syncthreads();
#pragma unroll
        for (int kk = 0; kk < 2; kk++) {
            const int k8 = kk * 8;
            uint2 a2[4][4];
#pragma unroll
            for (int mt = 0; mt < 4; mt++) {
                int r = wrow + mt * 16 + g;
                a2[mt][0] = A2[k8 + t][r];
                a2[mt][1] = A2[k8 + t][r + 8];
                a2[mt][2] = A2[k8 + t + 4][r];
                a2[mt][3] = A2[k8 + t + 4][r + 8];
            }
            uint2 b2[4][2];
#pragma unroll
            for (int nt = 0; nt < 4; nt++) {
                int c = wcol + nt * 8 + g;
                b2[nt][0] = B2[k8 + t][c];
                b2[nt][1] = B2[k8 + t + 4][c];
            }
#pragma unroll
            for (int mt = 0; mt < 4; mt++) {
                uint32_t ahi[4] = {a2[mt][0].x, a2[mt][1].x, a2[mt][2].x, a2[mt][3].x};
                uint32_t alo[4] = {a2[mt][0].y, a2[mt][1].y, a2[mt][2].y, a2[mt][3].y};
#pragma unroll
                for (int nt = 0; nt < 4; nt++) {
                    uint32_t bhi[2] = {b2[nt][0].x, b2[nt][1].x};
                    uint32_t blo[2] = {b2[nt][0].y, b2[nt][1].y};
                    mma_tf32(acc[mt][nt], alo, bhi);
                    mma_tf32(acc[mt][nt], ahi, blo);
                    mma_tf32(acc[mt][nt], ahi, bhi);
                }
            }
        }
    }

#pragma unroll
    for (int mt = 0; mt < 4; mt++) {
#pragma unroll
        for (int nt = 0; nt < 4; nt++) {
            int r0 = row0 + wrow + mt * 16 + g;
            int c = col0 + wcol + nt * 8 + 2 * t;
            float b0 = bias ? bias[c] : 0.f;
            float b1 = bias ? bias[c + 1] : 0.f;
            float v00 = acc[mt][nt][0] + b0, v01 = acc[mt][nt][1] + b1;
            float v10 = acc[mt][nt][2] + b0, v11 = acc[mt][nt][3] + b1;
            if (act == 1) {
                v00 = v00 > 0.f ? v00 : 0.01f * v00;
                v01 = v01 > 0.f ? v01 : 0.01f * v01;
                v10 = v10 > 0.f ? v10 : 0.01f * v10;
                v11 = v11 > 0.f ? v11 : 0.01f * v11;
            }
            if (r0 < M) {
                C[(size_t)r0 * N + c] = v00;
                C[(size_t)r0 * N + c + 1] = v01;
            }
            if (r0 + 8 < M) {
                C[(size_t)(r0 + 8) * N + c] = v10;
                C[(size_t)(r0 + 8) * N + c + 1] = v11;
            }
        }
    }
}

// ---------------- CSR build ----------------
__global__ void hist_kernel(const int* __restrict__ dst, int* __restrict__ deg, int n_e) {
    int e = blockIdx.x * blockDim.x + threadIdx.x;
    if (e < n_e) atomicAdd(&deg[dst[e]], 1);
}

// per-block exclusive scan over chunks of 1024 (256 threads x 4 elems)
__global__ void scan_block(const int* __restrict__ in, int* __restrict__ out,
                           int* __restrict__ bsum, int n) {
    __shared__ int s[256];
    int t = threadIdx.x;
    int base = blockIdx.x * 1024 + t * 4;
    int v[4];
#pragma unroll
    for (int j = 0; j < 4; j++) v[j] = (base + j < n) ? in[base + j] : 0;
    int tsum = v[0] + v[1] + v[2] + v[3];
    s[t] = tsum;
    __syncthreads();
    for (int off = 1; off < 256; off <<= 1) {
        int x = (t >= off) ? s[t - off] : 0;
        __syncthreads();
        s[t] += x;
        __syncthreads();
    }
    int exc = s[t] - tsum;
    if (t == 255) bsum[blockIdx.x] = s[t];
    int run = exc;
#pragma unroll
    for (int j = 0; j < 4; j++) {
        if (base + j < n) out[base + j] = run;
        run += v[j];
    }
}

__global__ void scan_bsum(int* __restrict__ bsum, int nb) {
    __shared__ int s[128];
    int t = threadIdx.x;
    int orig = (t < nb) ? bsum[t] : 0;
    s[t] = orig;
    __syncthreads();
    for (int off = 1; off < 128; off <<= 1) {
        int x = (t >= off) ? s[t - off] : 0;
        __syncthreads();
        s[t] += x;
        __syncthreads();
    }
    if (t < nb) bsum[t] = s[t] - orig;
}

__global__ void scan_fixup(int* __restrict__ ptr, const int* __restrict__ bsum,
                           int* __restrict__ cur, int n, int total) {
    int i = blockIdx.x * blockDim.x + threadIdx.x;
    if (i < n) {
        int p = ptr[i] + bsum[i >> 10];
        ptr[i] = p;
        cur[i] = p;
    }
    if (i == 0) ptr[n] = total;
}

__global__ void scatter_csr(const int* __restrict__ src, const int* __restrict__ dst,
                            int* __restrict__ cur, int* __restrict__ csr_src, int n_e) {
    int e = blockIdx.x * blockDim.x + threadIdx.x;
    if (e >= n_e) return;
    int p = atomicAdd(&cur[dst[e]], 1);
    csr_src[p] = src[e];
}

__global__ void build_gptr(const int* __restrict__ batch, int* __restrict__ gptr, int n) {
    int i = blockIdx.x * blockDim.x + threadIdx.x;
    if (i >= n) return;
    int b = batch[i];
    int prev = (i == 0) ? -1 : batch[i - 1];
    for (int g = prev + 1; g <= b; g++) gptr[g] = i;
    if (i == n - 1)
        for (int g = b + 1; g <= GG; g++) gptr[g] = n;
}

// ---------------- fused GAT aggregation (warp per destination node) ----------------
// h[row] = elu( (sum_e w_e * xw[src_e]) / (sum w + 1e-16) + bias ),
// w_e = exp(lrelu(asrc[src_e] + adst[row]) - max)
__global__ void gat_aggregate(const int* __restrict__ ptr, const int* __restrict__ csr,
                              const float* __restrict__ asrc, const float* __restrict__ adst,
                              const float* __restrict__ xw, const float* __restrict__ bias,
                              float* __restrict__ h, int n_rows) {
    int row = blockIdx.x * 8 + (threadIdx.x >> 5);
    int lane = threadIdx.x & 31;
    if (row >= n_rows) return;
    int start = ptr[row], end = ptr[row + 1];
    float ad = adst[row];

    float m = -INFINITY;
    for (int e = start + lane; e < end; e += 32) {
        float a = asrc[csr[e]] + ad;
        a = a > 0.f ? a : 0.01f * a;
        m = fmaxf(m, a);
    }
    m = warp_max_all(m);

    float4 acc = make_float4(0.f, 0.f, 0.f, 0.f);
    float sum = 0.f;
    for (int base = start; base < end; base += 32) {
        int e = base + lane;
        float w = 0.f;
        int s = 0;
        if (e < end) {
            s = csr[e];
            float a = asrc[s] + ad;
            a = a > 0.f ? a : 0.01f * a;
            w = expf(a - m);
            sum += w;
        }
        int cnt = min(32, end - base);
        for (int j = 0; j < cnt; j++) {
            float wj = __shfl_sync(FULL, w, j);
            int sj = __shfl_sync(FULL, s, j);
            float4 v = ((const float4*)(xw + (size_t)sj * HH))[lane];
            acc.x += wj * v.x;
            acc.y += wj * v.y;
            acc.z += wj * v.z;
            acc.w += wj * v.w;
        }
    }
    sum = warp_sum_all(sum);
    float rinv = 1.f / (sum + 1e-16f);
    float4 b4 = ((const float4*)bias)[lane];
    float4 o;
    o.x = acc.x * rinv + b4.x;
    o.y = acc.y * rinv + b4.y;
    o.z = acc.z * rinv + b4.z;
    o.w = acc.w * rinv + b4.w;
    o.x = o.x > 0.f ? o.x : expf(o.x) - 1.f;
    o.y = o.y > 0.f ? o.y : expf(o.y) - 1.f;
    o.z = o.z > 0.f ? o.z : expf(o.z) - 1.f;
    o.w = o.w > 0.f ? o.w : expf(o.w) - 1.f;
    ((float4*)(h + (size_t)row * HH))[lane] = o;
}

// ---------------- GATEConv per-node attention scalars ----------------
__global__ void gate_node_atts(const float* __restrict__ tmp, const float* __restrict__ W1,
                               const float* __restrict__ att_l, const float* __restrict__ x0,
                               const float* __restrict__ att_r, float* __restrict__ asrc,
                               float* __restrict__ adst, int n_rows) {
    int w = (blockIdx.x * blockDim.x + threadIdx.x) >> 5;
    int lane = threadIdx.x & 31;
    if (w >= n_rows) return;
    float4 tv = ((const float4*)(tmp + (size_t)w * HH))[lane];
    float4 xv = ((const float4*)(x0 + (size_t)w * HH))[lane];
    float s1 = 0.f, s2 = 0.f;
    const float* t = &tv.x;
    const float* xp = &xv.x;
#pragma unroll
    for (int j = 0; j < 4; j++) {
        int k = lane * 4 + j;
        float xe = t[j] + W1[(size_t)k * (HH + 1) + HH];
        xe = xe > 0.f ? xe : 0.01f * xe;
        s1 += xe * att_l[k];
        s2 += xp[j] * att_r[k];
    }
    s1 = warp_sum_all(s1);
    s2 = warp_sum_all(s2);
    if (lane == 0) { asrc[w] = s1; adst[w] = s2; }
}

__global__ void node_two_dots(const float* __restrict__ xw, const float* __restrict__ v1,
                              const float* __restrict__ v2, float* __restrict__ o1,
                              float* __restrict__ o2, int n_rows) {
    int w = (blockIdx.x * blockDim.x + threadIdx.x) >> 5;
    int lane = threadIdx.x & 31;
    if (w >= n_rows) return;
    float4 xv = ((const float4*)(xw + (size_t)w * HH))[lane];
    const float* xp = &xv.x;
    float s1 = 0.f, s2 = 0.f;
#pragma unroll
    for (int j = 0; j < 4; j++) {
        int k = lane * 4 + j;
        s1 += xp[j] * v1[k];
        s2 += xp[j] * v2[k];
    }
    s1 = warp_sum_all(s1);
    s2 = warp_sum_all(s2);
    if (lane == 0) { o1[w] = s1; o2[w] = s2; }
}

__global__ void node_one_dot(const float* __restrict__ xw, const float* __restrict__ v1,
                             float* __restrict__ o1, int n_rows) {
    int w = (blockIdx.x * blockDim.x + threadIdx.x) >> 5;
    int lane = threadIdx.x & 31;
    if (w >= n_rows) return;
    float4 xv = ((const float4*)(xw + (size_t)w * HH))[lane];
    const float* xp = &xv.x;
    float s1 = 0.f;
#pragma unroll
    for (int j = 0; j < 4; j++) s1 += xp[j] * v1[lane * 4 + j];
    s1 = warp_sum_all(s1);
    if (lane == 0) o1[w] = s1;
}

// ---------------- GRU combine + relu ----------------
__global__ void gru_combine(const float* __restrict__ gi, const float* __restrict__ gh,
                            const float* __restrict__ hprev, float* __restrict__ outp, int rows) {
    int idx = blockIdx.x * blockDim.x + threadIdx.x;
    if (idx >= rows * HH) return;
    int r = idx / HH, c = idx - r * HH;
    const float* gir = gi + (size_t)r * H3;
    const float* ghr = gh + (size_t)r * H3;
    float ir = gir[c], iz = gir[c + HH], in_ = gir[c + 2 * HH];
    float hr = ghr[c], hz = ghr[c + HH], hn = ghr[c + 2 * HH];
    float rr = 1.f / (1.f + expf(-(ir + hr)));
    float z = 1.f / (1.f + expf(-(iz + hz)));
    float n = tanhf(in_ + rr * hn);
    float o = (1.f - z) * n + z * hprev[idx];
    outp[idx] = o > 0.f ? o : 0.f;
}

// ---------------- molecule readout (warp per graph) ----------------
__global__ void graph_sum(const float* __restrict__ xc, const int* __restrict__ gptr,
                          float* __restrict__ outG, int n_g) {
    int g = blockIdx.x * 8 + (threadIdx.x >> 5);
    int lane = threadIdx.x & 31;
    if (g >= n_g) return;
    int start = gptr[g], end = gptr[g + 1];
    float4 acc = make_float4(0.f, 0.f, 0.f, 0.f);
    for (int i = start; i < end; i++) {
        float4 v = ((const float4*)(xc + (size_t)i * HH))[lane];
        acc.x += v.x; acc.y += v.y; acc.z += v.z; acc.w += v.w;
    }
    acc.x = fmaxf(acc.x, 0.f);
    acc.y = fmaxf(acc.y, 0.f);
    acc.z = fmaxf(acc.z, 0.f);
    acc.w = fmaxf(acc.w, 0.f);
    ((float4*)(outG + (size_t)g * HH))[lane] = acc;
}

__global__ void compute_vvec(const float* __restrict__ molW, const float* __restrict__ attdst,
                             float* __restrict__ v) {
    int k = threadIdx.x;
    float s = 0.f;
    for (int j = 0; j < HH; j++) s += molW[(size_t)j * HH + k] * attdst[j];
    v[k] = s;
}

// fused mol timestep: adst = outG[g].vvec, softmax over nodes of g, hG = elu(norm + bias)
__global__ void mol_timestep(const float* __restrict__ outG, const float* __restrict__ vvec,
                             const int* __restrict__ gptr, const float* __restrict__ asrc,
                             const float* __restrict__ xw, const float* __restrict__ bias,
                             float* __restrict__ hG, int n_g) {
    int g = blockIdx.x * 8 + (threadIdx.x >> 5);
    int lane = threadIdx.x & 31;
    if (g >= n_g) return;
    float4 ov = ((const float4*)(outG + (size_t)g * HH))[lane];
    float4 vv = ((const float4*)vvec)[lane];
    float ad = warp_sum_all(ov.x * vv.x + ov.y * vv.y + ov.z * vv.z + ov.w * vv.w);

    int start = gptr[g], end = gptr[g + 1];
    float m = -INFINITY;
    for (int i = start + lane; i < end; i += 32) {
        float a = asrc[i] + ad;
        a = a > 0.f ? a : 0.01f * a;
        m = fmaxf(m, a);
    }
    m = warp_max_all(m);

    float4 acc = make_float4(0.f, 0.f, 0.f, 0.f);
    float sum = 0.f;
    for (int base = start; base < end; base += 32) {
        int i = base + lane;
        float w = 0.f;
        if (i < end) {
            float a = asrc[i] + ad;
            a = a > 0.f ? a : 0.01f * a;
            w = expf(a - m);
            sum += w;
        }
        int cnt = min(32, end - base);
        for (int j = 0; j < cnt; j++) {
            float wj = __shfl_sync(FULL, w, j);
            float4 v = ((const float4*)(xw + (size_t)(base + j) * HH))[lane];
            acc.x += wj * v.x;
            acc.y += wj * v.y;
            acc.z += wj * v.z;
            acc.w += wj * v.w;
        }
    }
    sum = warp_sum_all(sum);
    float rinv = 1.f / (sum + 1e-16f);
    float4 b4 = ((const float4*)bias)[lane];
    float4 o;
    o.x = acc.x * rinv + b4.x;
    o.y = acc.y * rinv + b4.y;
    o.z = acc.z * rinv + b4.z;
    o.w = acc.w * rinv + b4.w;
    o.x = o.x > 0.f ? o.x : expf(o.x) - 1.f;
    o.y = o.y > 0.f ? o.y : expf(o.y) - 1.f;
    o.z = o.z > 0.f ? o.z : expf(o.z) - 1.f;
    o.w = o.w > 0.f ? o.w : expf(o.w) - 1.f;
    ((float4*)(hG + (size_t)g * HH))[lane] = o;
}

__global__ void final_out(const float* __restrict__ outG, const float* __restrict__ W,
                          const float* __restrict__ b, float* __restrict__ y, int g_rows) {
    int g = (blockIdx.x * blockDim.x + threadIdx.x) >> 5;
    int lane = threadIdx.x & 31;
    if (g >= g_rows) return;
    float4 v = ((const float4*)(outG + (size_t)g * HH))[lane];
    const float* vp = &v.x;
    float s = 0.f;
#pragma unroll
    for (int j = 0; j < 4; j++) s += vp[j] * W[lane * 4 + j];
    s = warp_sum_all(s);
    if (lane == 0) y[g] = s + b[0];
}

// ---------------- host ----------------
static inline int cdiv(int a, int b) { return (a + b - 1) / b; }

extern "C" void kernel_launch(void* const* d_in, const int* in_sizes, int n_in,
                              void* d_out, int out_size) {
    const float* x = (const float*)d_in[0];
    const int* ei = (const int*)d_in[1];
    const int* batch = (const int*)d_in[2];
    const float* lin1_W = (const float*)d_in[3];
    const float* lin1_b = (const float*)d_in[4];
    const float* gate_W1 = (const float*)d_in[5];
    const float* gate_W2 = (const float*)d_in[6];
    const float* gate_att_l = (const float*)d_in[7];
    const float* gate_att_r = (const float*)d_in[8];
    const float* gate_bias = (const float*)d_in[9];
    const float* gru0_Wi = (const float*)d_in[10];
    const float* gru0_bi = (const float*)d_in[11];
    const float* gru0_Wh = (const float*)d_in[12];
    const float* gru0_bh = (const float*)d_in[13];
    const float* atom_W = (const float*)d_in[14];
    const float* atom_att_src = (const float*)d_in[15];
    const float* atom_att_dst = (const float*)d_in[16];
    const float* atom_bias = (const float*)d_in[17];
    const float* atom_gru_Wi = (const float*)d_in[18];
    const float* atom_gru_bi = (const float*)d_in[19];
    const float* atom_gru_Wh = (const float*)d_in[20];
    const float* atom_gru_bh = (const float*)d_in[21];
    const float* mol_W = (const float*)d_in[22];
    const float* mol_att_src = (const float*)d_in[23];
    const float* mol_att_dst = (const float*)d_in[24];
    const float* mol_bias = (const float*)d_in[25];
    const float* mol_gru_Wi = (const float*)d_in[26];
    const float* mol_gru_bi = (const float*)d_in[27];
    const float* mol_gru_Wh = (const float*)d_in[28];
    const float* mol_gru_bh = (const float*)d_in[29];
    const float* lin2_W = (const float*)d_in[30];
    const float* lin2_b = (const float*)d_in[31];

    const int* src = ei;
    const int* dst = ei + EE;

    float *x0, *xw, *h, *xc, *gi, *gh, *asrc, *adst;
    float *outG, *hG, *giG, *ghG, *vvec;
    int *deg, *ptr, *cur, *csr_src, *bsum, *gptr;
    cudaGetSymbolAddress((void**)&x0, d_x0);
    cudaGetSymbolAddress((void**)&xw, d_xw);
    cudaGetSymbolAddress((void**)&h, d_h);
    cudaGetSymbolAddress((void**)&xc, d_xc);
    cudaGetSymbolAddress((void**)&gi, d_gi);
    cudaGetSymbolAddress((void**)&gh, d_gh);
    cudaGetSymbolAddress((void**)&asrc, d_asrc);
    cudaGetSymbolAddress((void**)&adst, d_adst);
    cudaGetSymbolAddress((void**)&outG, d_outG);
    cudaGetSymbolAddress((void**)&hG, d_hG);
    cudaGetSymbolAddress((void**)&giG, d_giG);
    cudaGetSymbolAddress((void**)&ghG, d_ghG);
    cudaGetSymbolAddress((void**)&vvec, d_vvec);
    cudaGetSymbolAddress((void**)&deg, d_deg);
    cudaGetSymbolAddress((void**)&ptr, d_ptr);
    cudaGetSymbolAddress((void**)&cur, d_cur);
    cudaGetSymbolAddress((void**)&csr_src, d_csr_src);
    cudaGetSymbolAddress((void**)&bsum, d_bsum);
    cudaGetSymbolAddress((void**)&gptr, d_gptr);

    dim3 g_n128(1, cdiv(NN, 128));
    dim3 g_n384(3, cdiv(NN, 128));
    dim3 g_g384(3, cdiv(GG, 128));
    int wpb_n = cdiv(NN, 8);
    int wpb_g = cdiv(GG, 8);
    const int nscan = cdiv(NN, 1024);

    // ---- CSR + graph-pointer build ----
    cudaMemsetAsync(deg, 0, NN * sizeof(int));
    hist_kernel<<<cdiv(EE, 256), 256>>>(dst, deg, EE);
    scan_block<<<nscan, 256>>>(deg, ptr, bsum, NN);
    scan_bsum<<<1, 128>>>(bsum, nscan);
    scan_fixup<<<cdiv(NN, 256), 256>>>(ptr, bsum, cur, NN, EE);
    scatter_csr<<<cdiv(EE, 256), 256>>>(src, dst, cur, csr_src, EE);
    build_gptr<<<cdiv(NN, 256), 256>>>(batch, gptr, NN);

    // x0 = lrelu(x @ lin1_W^T + b)
    sgemm<<<g_n128, 256>>>(x, lin1_W, lin1_b, x0, NN, HH, IN_CH, IN_CH, 1);

    // ---- GATEConv ----
    sgemm<<<g_n128, 256>>>(x0, gate_W1, nullptr, xw, NN, HH, HH, HH + 1, 0);
    gate_node_atts<<<wpb_n, 256>>>(xw, gate_W1, gate_att_l, x0, gate_att_r, asrc, adst, NN);
    sgemm<<<g_n128, 256>>>(x0, gate_W2, nullptr, xw, NN, HH, HH, HH, 0);
    gat_aggregate<<<wpb_n, 256>>>(ptr, csr_src, asrc, adst, xw, gate_bias, h, NN);
    sgemm<<<g_n384, 256>>>(h, gru0_Wi, gru0_bi, gi, NN, H3, HH, HH, 0);
    sgemm<<<g_n384, 256>>>(x0, gru0_Wh, gru0_bh, gh, NN, H3, HH, HH, 0);
    gru_combine<<<cdiv(NN * HH, 256), 256>>>(gi, gh, x0, xc, NN);

    // ---- extra atom GAT + GRU layers ----
    for (int l = 0; l < 2; l++) {
        sgemm<<<g_n128, 256>>>(xc, atom_W + (size_t)l * HH * HH, nullptr, xw, NN, HH, HH, HH, 0);
        node_two_dots<<<wpb_n, 256>>>(xw, atom_att_src + l * HH, atom_att_dst + l * HH, asrc, adst, NN);
        gat_aggregate<<<wpb_n, 256>>>(ptr, csr_src, asrc, adst, xw, atom_bias + l * HH, h, NN);
        sgemm<<<g_n384, 256>>>(h, atom_gru_Wi + (size_t)l * H3 * HH, atom_gru_bi + l * H3, gi, NN, H3, HH, HH, 0);
        sgemm<<<g_n384, 256>>>(xc, atom_gru_Wh + (size_t)l * H3 * HH, atom_gru_bh + l * H3, gh, NN, H3, HH, HH, 0);
        gru_combine<<<cdiv(NN * HH, 256), 256>>>(gi, gh, xc, xc, NN);
    }

    // ---- molecule readout ----
    graph_sum<<<wpb_g, 256>>>(xc, gptr, outG, GG);
    sgemm<<<g_n128, 256>>>(xc, mol_W, nullptr, xw, NN, HH, HH, HH, 0);
    node_one_dot<<<wpb_n, 256>>>(xw, mol_att_src, asrc, NN);
    compute_vvec<<<1, HH>>>(mol_W, mol_att_dst, vvec);

    for (int t = 0; t < 2; t++) {
        mol_timestep<<<wpb_g, 256>>>(outG, vvec, gptr, asrc, xw, mol_bias, hG, GG);
        sgemm<<<g_g384, 256>>>(hG, mol_gru_Wi, mol_gru_bi, giG, GG, H3, HH, HH, 0);
        sgemm<<<g_g384, 256>>>(outG, mol_gru_Wh, mol_gru_bh, ghG, GG, H3, HH, HH, 0);
        gru_combine<<<cdiv(GG * HH, 256), 256>>>(giG, ghG, outG, outG, GG);
    }

    final_out<<<wpb_g, 256>>>(outG, lin2_W, lin2_b, (float*)d_out, GG);
}

// round 5
// speedup vs baseline: 2.4271x; 1.1021x over previous
#include <cuda_runtime.h>
#include <math.h>
#include <stdint.h>

#define NN 100000
#define EE 1600000
#define IN_CH 64
#define HH 128
#define H3 384
#define GG 4096
#define FULL 0xffffffffu

// ---------------- scratch (no allocations allowed) ----------------
__device__ float d_x0[NN * HH];
__device__ float d_xw[NN * HH];
__device__ float d_h[NN * HH];
__device__ float d_xc[NN * HH];
__device__ float d_gi[NN * H3];
__device__ float d_gh[NN * H3];
__device__ float d_asrc[NN];
__device__ float d_adst[NN];
__device__ float d_outG[GG * HH];
__device__ float d_hG[GG * HH];
__device__ float d_giG[GG * H3];
__device__ float d_ghG[GG * H3];
__device__ float d_vvec[HH];
__device__ int d_deg[NN];
__device__ int d_ptr[NN + 1];
__device__ int d_cur[NN];
__device__ int d_csr_src[EE];
__device__ int d_bsum[128];
__device__ int d_gptr[GG + 1];

// ---------------- helpers ----------------
__device__ __forceinline__ float warp_sum_all(float v) {
#pragma unroll
    for (int o = 16; o > 0; o >>= 1) v += __shfl_xor_sync(FULL, v, o);
    return v;
}
__device__ __forceinline__ float warp_max_all(float v) {
#pragma unroll
    for (int o = 16; o > 0; o >>= 1) v = fmaxf(v, __shfl_xor_sync(FULL, v, o));
    return v;
}

__device__ __forceinline__ uint32_t f2tf32(float f) {
    uint32_t o;
    asm("cvt.rna.tf32.f32 %0, %1;" : "=r"(o) : "f"(f));
    return o;
}

__device__ __forceinline__ void mma_tf32(float* c, const uint32_t* a, const uint32_t* b) {
    asm volatile(
        "mma.sync.aligned.m16n8k8.row.col.f32.tf32.tf32.f32 "
        "{%0,%1,%2,%3}, {%4,%5,%6,%7}, {%8,%9}, {%0,%1,%2,%3};"
        : "+f"(c[0]), "+f"(c[1]), "+f"(c[2]), "+f"(c[3])
        : "r"(a[0]), "r"(a[1]), "r"(a[2]), "r"(a[3]), "r"(b[0]), "r"(b[1]));
}

__device__ __forceinline__ void cp_async16(uint32_t dst, const void* src, bool pred) {
    asm volatile("cp.async.cg.shared.global [%0], [%1], 16, %2;"
                 :: "r"(dst), "l"(src), "r"(pred ? 16 : 0));
}

// ---------------- pipelined tensor-core fp32 GEMM (3xTF32 split in registers) ----------------
// C[M,N] = act(A[M,K] @ B[N,K]^T + bias). N % 128 == 0, K % 16 == 0.
// act: 0 = none, 1 = leaky_relu(0.01)
__device__ __forceinline__ void gemm_prefetch(const float* __restrict__ A,
                                              const float* __restrict__ B,
                                              int M, int K, int ldb, bool b_vec,
                                              int row0, int col0, int tid, int k0,
                                              float (*As)[20], float (*Bs)[20]) {
#pragma unroll
    for (int it = 0; it < 2; it++) {
        int seg = tid * 2 + it;          // 0..511
        int r = seg >> 2;                // 0..127
        int kg = (seg & 3) << 2;         // 0,4,8,12
        int ar = row0 + r;
        uint32_t da = (uint32_t)__cvta_generic_to_shared(&As[r][kg]);
        cp_async16(da, A + (size_t)ar * K + k0 + kg, ar < M);
        if (b_vec) {
            uint32_t db = (uint32_t)__cvta_generic_to_shared(&Bs[r][kg]);
            cp_async16(db, B + (size_t)(col0 + r) * ldb + k0 + kg, true);
        } else {
            const float* bp = B + (size_t)(col0 + r) * ldb + k0 + kg;
#pragma unroll
            for (int j = 0; j < 4; j++) Bs[r][kg + j] = bp[j];
        }
    }
    asm volatile("cp.async.commit_group;");
}

__global__ void __launch_bounds__(256) sgemm(const float* __restrict__ A,
                                             const float* __restrict__ B,
                                             const float* __restrict__ bias,
                                             float* __restrict__ C,
                                             int M, int N, int K, int ldb, int act) {
    __shared__ float As[2][128][20];
    __shared__ float Bs[2][128][20];

    const int tid = threadIdx.x;
    const int lane = tid & 31;
    const int warp = tid >> 5;
    const int g = lane >> 2;
    const int t = lane & 3;
    const int wrow = (warp & 1) * 64;
    const int wcol = (warp >> 1) * 32;
    const int row0 = blockIdx.y * 128;
    const int col0 = blockIdx.x * 128;

    float acc[4][4][4];
#pragma unroll
    for (int mt = 0; mt < 4; mt++)
#pragma unroll
        for (int nt = 0; nt < 4; nt++)
#pragma unroll
            for (int i = 0; i < 4; i++) acc[mt][nt][i] = 0.f;

    const bool b_vec = ((ldb & 3) == 0);
    const int nk = K >> 4;

    gemm_prefetch(A, B, M, K, ldb, b_vec, row0, col0, tid, 0, As[0], Bs[0]);

    for (int c = 0; c < nk; c++) {
        asm volatile("cp.async.wait_group 0;");
        __syncthreads();
        if (c + 1 < nk)
            gemm_prefetch(A, B, M, K, ldb, b_vec, row0, col0, tid, (c + 1) << 4,
                          As[(c + 1) & 1], Bs[(c + 1) & 1]);
        const float (*Asb)[20] = As[c & 1];
        const float (*Bsb)[20] = Bs[c & 1];
#pragma unroll
        for (int kk = 0; kk < 2; kk++) {
            const int k8 = kk * 8;
            // load raw f32 fragments and split to hi/lo tf32 in registers
            uint32_t ahi[4][4], alo[4][4];
#pragma unroll
            for (int mt = 0; mt < 4; mt++) {
                int r = wrow + mt * 16 + g;
                float f0 = Asb[r][k8 + t];
                float f1 = Asb[r + 8][k8 + t];
                float f2 = Asb[r][k8 + t + 4];
                float f3 = Asb[r + 8][k8 + t + 4];
                ahi[mt][0] = f2tf32(f0); alo[mt][0] = f2tf32(f0 - __uint_as_float(ahi[mt][0]));
                ahi[mt][1] = f2tf32(f1); alo[mt][1] = f2tf32(f1 - __uint_as_float(ahi[mt][1]));
                ahi[mt][2] = f2tf32(f2); alo[mt][2] = f2tf32(f2 - __uint_as_float(ahi[mt][2]));
                ahi[mt][3] = f2tf32(f3); alo[mt][3] = f2tf32(f3 - __uint_as_float(ahi[mt][3]));
            }
            uint32_t bhi[4][2], blo[4][2];
#pragma unroll
            for (int nt = 0; nt < 4; nt++) {
                int cc = wcol + nt * 8 + g;
                float f0 = Bsb[cc][k8 + t];
                float f1 = Bsb[cc][k8 + t + 4];
                bhi[nt][0] = f2tf32(f0); blo[nt][0] = f2tf32(f0 - __uint_as_float(bhi[nt][0]));
                bhi[nt][1] = f2tf32(f1); blo[nt][1] = f2tf32(f1 - __uint_as_float(bhi[nt][1]));
            }
#pragma unroll
            for (int mt = 0; mt < 4; mt++)
#pragma unroll
                for (int nt = 0; nt < 4; nt++) {
                    mma_tf32(acc[mt][nt], alo[mt], bhi[nt]);
                    mma_tf32(acc[mt][nt], ahi[mt], blo[nt]);
                    mma_tf32(acc[mt][nt], ahi[mt], bhi[nt]);
                }
        }
        __syncthreads();
    }

#pragma unroll
    for (int mt = 0; mt < 4; mt++) {
#pragma unroll
        for (int nt = 0; nt < 4; nt++) {
            int r0 = row0 + wrow + mt * 16 + g;
            int c = col0 + wcol + nt * 8 + 2 * t;
            float b0 = bias ? bias[c] : 0.f;
            float b1 = bias ? bias[c + 1] : 0.f;
            float v00 = acc[mt][nt][0] + b0, v01 = acc[mt][nt][1] + b1;
            float v10 = acc[mt][nt][2] + b0, v11 = acc[mt][nt][3] + b1;
            if (act == 1) {
                v00 = v00 > 0.f ? v00 : 0.01f * v00;
                v01 = v01 > 0.f ? v01 : 0.01f * v01;
                v10 = v10 > 0.f ? v10 : 0.01f * v10;
                v11 = v11 > 0.f ? v11 : 0.01f * v11;
            }
            if (r0 < M) {
                C[(size_t)r0 * N + c] = v00;
                C[(size_t)r0 * N + c + 1] = v01;
            }
            if (r0 + 8 < M) {
                C[(size_t)(r0 + 8) * N + c] = v10;
                C[(size_t)(r0 + 8) * N + c + 1] = v11;
            }
        }
    }
}

// ---------------- CSR build ----------------
__global__ void hist_kernel(const int* __restrict__ dst, int* __restrict__ deg, int n_e) {
    int e = blockIdx.x * blockDim.x + threadIdx.x;
    if (e < n_e) atomicAdd(&deg[dst[e]], 1);
}

__global__ void scan_block(const int* __restrict__ in, int* __restrict__ out,
                           int* __restrict__ bsum, int n) {
    __shared__ int s[256];
    int t = threadIdx.x;
    int base = blockIdx.x * 1024 + t * 4;
    int v[4];
#pragma unroll
    for (int j = 0; j < 4; j++) v[j] = (base + j < n) ? in[base + j] : 0;
    int tsum = v[0] + v[1] + v[2] + v[3];
    s[t] = tsum;
    __syncthreads();
    for (int off = 1; off < 256; off <<= 1) {
        int x = (t >= off) ? s[t - off] : 0;
        __syncthreads();
        s[t] += x;
        __syncthreads();
    }
    int exc = s[t] - tsum;
    if (t == 255) bsum[blockIdx.x] = s[t];
    int run = exc;
#pragma unroll
    for (int j = 0; j < 4; j++) {
        if (base + j < n) out[base + j] = run;
        run += v[j];
    }
}

__global__ void scan_bsum(int* __restrict__ bsum, int nb) {
    __shared__ int s[128];
    int t = threadIdx.x;
    int orig = (t < nb) ? bsum[t] : 0;
    s[t] = orig;
    __syncthreads();
    for (int off = 1; off < 128; off <<= 1) {
        int x = (t >= off) ? s[t - off] : 0;
        __syncthreads();
        s[t] += x;
        __syncthreads();
    }
    if (t < nb) bsum[t] = s[t] - orig;
}

__global__ void scan_fixup(int* __restrict__ ptr, const int* __restrict__ bsum,
                           int* __restrict__ cur, int n, int total) {
    int i = blockIdx.x * blockDim.x + threadIdx.x;
    if (i < n) {
        int p = ptr[i] + bsum[i >> 10];
        ptr[i] = p;
        cur[i] = p;
    }
    if (i == 0) ptr[n] = total;
}

__global__ void scatter_csr(const int* __restrict__ src, const int* __restrict__ dst,
                            int* __restrict__ cur, int* __restrict__ csr_src, int n_e) {
    int e = blockIdx.x * blockDim.x + threadIdx.x;
    if (e >= n_e) return;
    int p = atomicAdd(&cur[dst[e]], 1);
    csr_src[p] = src[e];
}

__global__ void build_gptr(const int* __restrict__ batch, int* __restrict__ gptr, int n) {
    int i = blockIdx.x * blockDim.x + threadIdx.x;
    if (i >= n) return;
    int b = batch[i];
    int prev = (i == 0) ? -1 : batch[i - 1];
    for (int g = prev + 1; g <= b; g++) gptr[g] = i;
    if (i == n - 1)
        for (int g = b + 1; g <= GG; g++) gptr[g] = n;
}

// ---------------- fused GAT aggregation (warp per destination node) ----------------
__global__ void gat_aggregate(const int* __restrict__ ptr, const int* __restrict__ csr,
                              const float* __restrict__ asrc, const float* __restrict__ adst,
                              const float* __restrict__ xw, const float* __restrict__ bias,
                              float* __restrict__ h, int n_rows) {
    int row = blockIdx.x * 8 + (threadIdx.x >> 5);
    int lane = threadIdx.x & 31;
    if (row >= n_rows) return;
    int start = ptr[row], end = ptr[row + 1];
    float ad = adst[row];

    float m = -INFINITY;
    for (int e = start + lane; e < end; e += 32) {
        float a = asrc[csr[e]] + ad;
        a = a > 0.f ? a : 0.01f * a;
        m = fmaxf(m, a);
    }
    m = warp_max_all(m);

    float4 acc = make_float4(0.f, 0.f, 0.f, 0.f);
    float sum = 0.f;
    for (int base = start; base < end; base += 32) {
        int e = base + lane;
        float w = 0.f;
        int s = 0;
        if (e < end) {
            s = csr[e];
            float a = asrc[s] + ad;
            a = a > 0.f ? a : 0.01f * a;
            w = expf(a - m);
            sum += w;
        }
        int cnt = min(32, end - base);
        for (int j = 0; j < cnt; j++) {
            float wj = __shfl_sync(FULL, w, j);
            int sj = __shfl_sync(FULL, s, j);
            float4 v = ((const float4*)(xw + (size_t)sj * HH))[lane];
            acc.x += wj * v.x;
            acc.y += wj * v.y;
            acc.z += wj * v.z;
            acc.w += wj * v.w;
        }
    }
    sum = warp_sum_all(sum);
    float rinv = 1.f / (sum + 1e-16f);
    float4 b4 = ((const float4*)bias)[lane];
    float4 o;
    o.x = acc.x * rinv + b4.x;
    o.y = acc.y * rinv + b4.y;
    o.z = acc.z * rinv + b4.z;
    o.w = acc.w * rinv + b4.w;
    o.x = o.x > 0.f ? o.x : expf(o.x) - 1.f;
    o.y = o.y > 0.f ? o.y : expf(o.y) - 1.f;
    o.z = o.z > 0.f ? o.z : expf(o.z) - 1.f;
    o.w = o.w > 0.f ? o.w : expf(o.w) - 1.f;
    ((float4*)(h + (size_t)row * HH))[lane] = o;
}

// ---------------- GATEConv per-node attention scalars ----------------
__global__ void gate_node_atts(const float* __restrict__ tmp, const float* __restrict__ W1,
                               const float* __restrict__ att_l, const float* __restrict__ x0,
                               const float* __restrict__ att_r, float* __restrict__ asrc,
                               float* __restrict__ adst, int n_rows) {
    int w = (blockIdx.x * blockDim.x + threadIdx.x) >> 5;
    int lane = threadIdx.x & 31;
    if (w >= n_rows) return;
    float4 tv = ((const float4*)(tmp + (size_t)w * HH))[lane];
    float4 xv = ((const float4*)(x0 + (size_t)w * HH))[lane];
    float s1 = 0.f, s2 = 0.f;
    const float* t = &tv.x;
    const float* xp = &xv.x;
#pragma unroll
    for (int j = 0; j < 4; j++) {
        int k = lane * 4 + j;
        float xe = t[j] + W1[(size_t)k * (HH + 1) + HH];
        xe = xe > 0.f ? xe : 0.01f * xe;
        s1 += xe * att_l[k];
        s2 += xp[j] * att_r[k];
    }
    s1 = warp_sum_all(s1);
    s2 = warp_sum_all(s2);
    if (lane == 0) { asrc[w] = s1; adst[w] = s2; }
}

__global__ void node_two_dots(const float* __restrict__ xw, const float* __restrict__ v1,
                              const float* __restrict__ v2, float* __restrict__ o1,
                              float* __restrict__ o2, int n_rows) {
    int w = (blockIdx.x * blockDim.x + threadIdx.x) >> 5;
    int lane = threadIdx.x & 31;
    if (w >= n_rows) return;
    float4 xv = ((const float4*)(xw + (size_t)w * HH))[lane];
    const float* xp = &xv.x;
    float s1 = 0.f, s2 = 0.f;
#pragma unroll
    for (int j = 0; j < 4; j++) {
        int k = lane * 4 + j;
        s1 += xp[j] * v1[k];
        s2 += xp[j] * v2[k];
    }
    s1 = warp_sum_all(s1);
    s2 = warp_sum_all(s2);
    if (lane == 0) { o1[w] = s1; o2[w] = s2; }
}

__global__ void node_one_dot(const float* __restrict__ xw, const float* __restrict__ v1,
                             float* __restrict__ o1, int n_rows) {
    int w = (blockIdx.x * blockDim.x + threadIdx.x) >> 5;
    int lane = threadIdx.x & 31;
    if (w >= n_rows) return;
    float4 xv = ((const float4*)(xw + (size_t)w * HH))[lane];
    const float* xp = &xv.x;
    float s1 = 0.f;
#pragma unroll
    for (int j = 0; j < 4; j++) s1 += xp[j] * v1[lane * 4 + j];
    s1 = warp_sum_all(s1);
    if (lane == 0) o1[w] = s1;
}

// ---------------- GRU combine + relu ----------------
__global__ void gru_combine(const float* __restrict__ gi, const float* __restrict__ gh,
                            const float* __restrict__ hprev, float* __restrict__ outp, int rows) {
    int idx = blockIdx.x * blockDim.x + threadIdx.x;
    if (idx >= rows * HH) return;
    int r = idx / HH, c = idx - r * HH;
    const float* gir = gi + (size_t)r * H3;
    const float* ghr = gh + (size_t)r * H3;
    float ir = gir[c], iz = gir[c + HH], in_ = gir[c + 2 * HH];
    float hr = ghr[c], hz = ghr[c + HH], hn = ghr[c + 2 * HH];
    float rr = 1.f / (1.f + expf(-(ir + hr)));
    float z = 1.f / (1.f + expf(-(iz + hz)));
    float n = tanhf(in_ + rr * hn);
    float o = (1.f - z) * n + z * hprev[idx];
    outp[idx] = o > 0.f ? o : 0.f;
}

// ---------------- molecule readout (warp per graph) ----------------
__global__ void graph_sum(const float* __restrict__ xc, const int* __restrict__ gptr,
                          float* __restrict__ outG, int n_g) {
    int g = blockIdx.x * 8 + (threadIdx.x >> 5);
    int lane = threadIdx.x & 31;
    if (g >= n_g) return;
    int start = gptr[g], end = gptr[g + 1];
    float4 acc = make_float4(0.f, 0.f, 0.f, 0.f);
    for (int i = start; i < end; i++) {
        float4 v = ((const float4*)(xc + (size_t)i * HH))[lane];
        acc.x += v.x; acc.y += v.y; acc.z += v.z; acc.w += v.w;
    }
    acc.x = fmaxf(acc.x, 0.f);
    acc.y = fmaxf(acc.y, 0.f);
    acc.z = fmaxf(acc.z, 0.f);
    acc.w = fmaxf(acc.w, 0.f);
    ((float4*)(outG + (size_t)g * HH))[lane] = acc;
}

__global__ void compute_vvec(const float* __restrict__ molW, const float* __restrict__ attdst,
                             float* __restrict__ v) {
    int k = threadIdx.x;
    float s = 0.f;
    for (int j = 0; j < HH; j++) s += molW[(size_t)j * HH + k] * attdst[j];
    v[k] = s;
}

__global__ void mol_timestep(const float* __restrict__ outG, const float* __restrict__ vvec,
                             const int* __restrict__ gptr, const float* __restrict__ asrc,
                             const float* __restrict__ xw, const float* __restrict__ bias,
                             float* __restrict__ hG, int n_g) {
    int g = blockIdx.x * 8 + (threadIdx.x >> 5);
    int lane = threadIdx.x & 31;
    if (g >= n_g) return;
    float4 ov = ((const float4*)(outG + (size_t)g * HH))[lane];
    float4 vv = ((const float4*)vvec)[lane];
    float ad = warp_sum_all(ov.x * vv.x + ov.y * vv.y + ov.z * vv.z + ov.w * vv.w);

    int start = gptr[g], end = gptr[g + 1];
    float m = -INFINITY;
    for (int i = start + lane; i < end; i += 32) {
        float a = asrc[i] + ad;
        a = a > 0.f ? a : 0.01f * a;
        m = fmaxf(m, a);
    }
    m = warp_max_all(m);

    float4 acc = make_float4(0.f, 0.f, 0.f, 0.f);
    float sum = 0.f;
    for (int base = start; base < end; base += 32) {
        int i = base + lane;
        float w = 0.f;
        if (i < end) {
            float a = asrc[i] + ad;
            a = a > 0.f ? a : 0.01f * a;
            w = expf(a - m);
            sum += w;
        }
        int cnt = min(32, end - base);
        for (int j = 0; j < cnt; j++) {
            float wj = __shfl_sync(FULL, w, j);
            float4 v = ((const float4*)(xw + (size_t)(base + j) * HH))[lane];
            acc.x += wj * v.x;
            acc.y += wj * v.y;
            acc.z += wj * v.z;
            acc.w += wj * v.w;
        }
    }
    sum = warp_sum_all(sum);
    float rinv = 1.f / (sum + 1e-16f);
    float4 b4 = ((const float4*)bias)[lane];
    float4 o;
    o.x = acc.x * rinv + b4.x;
    o.y = acc.y * rinv + b4.y;
    o.z = acc.z * rinv + b4.z;
    o.w = acc.w * rinv + b4.w;
    o.x = o.x > 0.f ? o.x : expf(o.x) - 1.f;
    o.y = o.y > 0.f ? o.y : expf(o.y) - 1.f;
    o.z = o.z > 0.f ? o.z : expf(o.z) - 1.f;
    o.w = o.w > 0.f ? o.w : expf(o.w) - 1.f;
    ((float4*)(hG + (size_t)g * HH))[lane] = o;
}

__global__ void final_out(const float* __restrict__ outG, const float* __restrict__ W,
                          const float* __restrict__ b, float* __restrict__ y, int g_rows) {
    int g = (blockIdx.x * blockDim.x + threadIdx.x) >> 5;
    int lane = threadIdx.x & 31;
    if (g >= g_rows) return;
    float4 v = ((const float4*)(outG + (size_t)g * HH))[lane];
    const float* vp = &v.x;
    float s = 0.f;
#pragma unroll
    for (int j = 0; j < 4; j++) s += vp[j] * W[lane * 4 + j];
    s = warp_sum_all(s);
    if (lane == 0) y[g] = s + b[0];
}

// ---------------- host ----------------
static inline int cdiv(int a, int b) { return (a + b - 1) / b; }

extern "C" void kernel_launch(void* const* d_in, const int* in_sizes, int n_in,
                              void* d_out, int out_size) {
    const float* x = (const float*)d_in[0];
    const int* ei = (const int*)d_in[1];
    const int* batch = (const int*)d_in[2];
    const float* lin1_W = (const float*)d_in[3];
    const float* lin1_b = (const float*)d_in[4];
    const float* gate_W1 = (const float*)d_in[5];
    const float* gate_W2 = (const float*)d_in[6];
    const float* gate_att_l = (const float*)d_in[7];
    const float* gate_att_r = (const float*)d_in[8];
    const float* gate_bias = (const float*)d_in[9];
    const float* gru0_Wi = (const float*)d_in[10];
    const float* gru0_bi = (const float*)d_in[11];
    const float* gru0_Wh = (const float*)d_in[12];
    const float* gru0_bh = (const float*)d_in[13];
    const float* atom_W = (const float*)d_in[14];
    const float* atom_att_src = (const float*)d_in[15];
    const float* atom_att_dst = (const float*)d_in[16];
    const float* atom_bias = (const float*)d_in[17];
    const float* atom_gru_Wi = (const float*)d_in[18];
    const float* atom_gru_bi = (const float*)d_in[19];
    const float* atom_gru_Wh = (const float*)d_in[20];
    const float* atom_gru_bh = (const float*)d_in[21];
    const float* mol_W = (const float*)d_in[22];
    const float* mol_att_src = (const float*)d_in[23];
    const float* mol_att_dst = (const float*)d_in[24];
    const float* mol_bias = (const float*)d_in[25];
    const float* mol_gru_Wi = (const float*)d_in[26];
    const float* mol_gru_bi = (const float*)d_in[27];
    const float* mol_gru_Wh = (const float*)d_in[28];
    const float* mol_gru_bh = (const float*)d_in[29];
    const float* lin2_W = (const float*)d_in[30];
    const float* lin2_b = (const float*)d_in[31];

    const int* src = ei;
    const int* dst = ei + EE;

    float *x0, *xw, *h, *xc, *gi, *gh, *asrc, *adst;
    float *outG, *hG, *giG, *ghG, *vvec;
    int *deg, *ptr, *cur, *csr_src, *bsum, *gptr;
    cudaGetSymbolAddress((void**)&x0, d_x0);
    cudaGetSymbolAddress((void**)&xw, d_xw);
    cudaGetSymbolAddress((void**)&h, d_h);
    cudaGetSymbolAddress((void**)&xc, d_xc);
    cudaGetSymbolAddress((void**)&gi, d_gi);
    cudaGetSymbolAddress((void**)&gh, d_gh);
    cudaGetSymbolAddress((void**)&asrc, d_asrc);
    cudaGetSymbolAddress((void**)&adst, d_adst);
    cudaGetSymbolAddress((void**)&outG, d_outG);
    cudaGetSymbolAddress((void**)&hG, d_hG);
    cudaGetSymbolAddress((void**)&giG, d_giG);
    cudaGetSymbolAddress((void**)&ghG, d_ghG);
    cudaGetSymbolAddress((void**)&vvec, d_vvec);
    cudaGetSymbolAddress((void**)&deg, d_deg);
    cudaGetSymbolAddress((void**)&ptr, d_ptr);
    cudaGetSymbolAddress((void**)&cur, d_cur);
    cudaGetSymbolAddress((void**)&csr_src, d_csr_src);
    cudaGetSymbolAddress((void**)&bsum, d_bsum);
    cudaGetSymbolAddress((void**)&gptr, d_gptr);

    dim3 g_n128(1, cdiv(NN, 128));
    dim3 g_n384(3, cdiv(NN, 128));
    dim3 g_g384(3, cdiv(GG, 128));
    int wpb_n = cdiv(NN, 8);
    int wpb_g = cdiv(GG, 8);
    const int nscan = cdiv(NN, 1024);

    // ---- CSR + graph-pointer build ----
    cudaMemsetAsync(deg, 0, NN * sizeof(int));
    hist_kernel<<<cdiv(EE, 256), 256>>>(dst, deg, EE);
    scan_block<<<nscan, 256>>>(deg, ptr, bsum, NN);
    scan_bsum<<<1, 128>>>(bsum, nscan);
    scan_fixup<<<cdiv(NN, 256), 256>>>(ptr, bsum, cur, NN, EE);
    scatter_csr<<<cdiv(EE, 256), 256>>>(src, dst, cur, csr_src, EE);
    build_gptr<<<cdiv(NN, 256), 256>>>(batch, gptr, NN);

    // x0 = lrelu(x @ lin1_W^T + b)
    sgemm<<<g_n128, 256>>>(x, lin1_W, lin1_b, x0, NN, HH, IN_CH, IN_CH, 1);

    // ---- GATEConv ----
    sgemm<<<g_n128, 256>>>(x0, gate_W1, nullptr, xw, NN, HH, HH, HH + 1, 0);
    gate_node_atts<<<wpb_n, 256>>>(xw, gate_W1, gate_att_l, x0, gate_att_r, asrc, adst, NN);
    sgemm<<<g_n128, 256>>>(x0, gate_W2, nullptr, xw, NN, HH, HH, HH, 0);
    gat_aggregate<<<wpb_n, 256>>>(ptr, csr_src, asrc, adst, xw, gate_bias, h, NN);
    sgemm<<<g_n384, 256>>>(h, gru0_Wi, gru0_bi, gi, NN, H3, HH, HH, 0);
    sgemm<<<g_n384, 256>>>(x0, gru0_Wh, gru0_bh, gh, NN, H3, HH, HH, 0);
    gru_combine<<<cdiv(NN * HH, 256), 256>>>(gi, gh, x0, xc, NN);

    // ---- extra atom GAT + GRU layers ----
    for (int l = 0; l < 2; l++) {
        sgemm<<<g_n128, 256>>>(xc, atom_W + (size_t)l * HH * HH, nullptr, xw, NN, HH, HH, HH, 0);
        node_two_dots<<<wpb_n, 256>>>(xw, atom_att_src + l * HH, atom_att_dst + l * HH, asrc, adst, NN);
        gat_aggregate<<<wpb_n, 256>>>(ptr, csr_src, asrc, adst, xw, atom_bias + l * HH, h, NN);
        sgemm<<<g_n384, 256>>>(h, atom_gru_Wi + (size_t)l * H3 * HH, atom_gru_bi + l * H3, gi, NN, H3, HH, HH, 0);
        sgemm<<<g_n384, 256>>>(xc, atom_gru_Wh + (size_t)l * H3 * HH, atom_gru_bh + l * H3, gh, NN, H3, HH, HH, 0);
        gru_combine<<<cdiv(NN * HH, 256), 256>>>(gi, gh, xc, xc, NN);
    }

    // ---- molecule readout ----
    graph_sum<<<wpb_g, 256>>>(xc, gptr, outG, GG);
    sgemm<<<g_n128, 256>>>(xc, mol_W, nullptr, xw, NN, HH, HH, HH, 0);
    node_one_dot<<<wpb_n, 256>>>(xw, mol_att_src, asrc, NN);
    compute_vvec<<<1, HH>>>(mol_W, mol_att_dst, vvec);

    for (int t = 0; t < 2; t++) {
        mol_timestep<<<wpb_g, 256>>>(outG, vvec, gptr, asrc, xw, mol_bias, hG, GG);
        sgemm<<<g_g384, 256>>>(hG, mol_gru_Wi, mol_gru_bi, giG, GG, H3, HH, HH, 0);
        sgemm<<<g_g384, 256>>>(outG, mol_gru_Wh, mol_gru_bh, ghG, GG, H3, HH, HH, 0);
        gru_combine<<<cdiv(GG * HH, 256), 256>>>(giG, ghG, outG, outG, GG);
    }

    final_out<<<wpb_g, 256>>>(outG, lin2_W, lin2_b, (float*)d_out, GG);
}